// round 7
// baseline (speedup 1.0000x reference)
#include <cuda_runtime.h>
#include <cuda_fp16.h>
#include <cstdint>

#define B_ 16
#define N_ 1024
#define FIN_ 64
#define H_ 256

// ===================== scratch (static device globals) =====================
__device__ __half    g_E    [B_ * N_ * N_];   // unnormalized masked exp (fp16), 32MB
__device__ __half    g_x16b [B_ * N_ * H_];   // layer1 output (fp16)
__device__ __half    g_h16  [B_ * N_ * H_];   // h natural layout [b][j][c]
__device__ __half    g_wf16 [FIN_ * H_];      // fused emb@W0 (fp16)
__device__ float     g_bf   [H_];             // fused bias emb_b@W0
__device__ __half    g_w116 [H_ * H_];
__device__ uint32_t  g_mask [B_ * N_ * 32];   // pair-interleaved ballot words
__device__ float     g_s1[B_ * N_], g_s2[B_ * N_], g_rl[B_ * N_];
__device__ float     g_psum[B_ * 8 * H_], g_pmax[B_ * 8 * H_];

// ===================== mma/ldmatrix/cp.async helpers (baseline PTX) ============
__device__ __forceinline__ uint32_t smem_u32(const void* p) {
    uint32_t a;
    asm("{ .reg .u64 t; cvta.to.shared.u64 t, %1; cvt.u32.u64 %0, t; }" : "=r"(a) : "l"(p));
    return a;
}
__device__ __forceinline__ void ldsm_x4(uint32_t& r0, uint32_t& r1, uint32_t& r2,
                                        uint32_t& r3, uint32_t addr) {
    asm volatile("ldmatrix.sync.aligned.m8n8.x4.shared.b16 {%0,%1,%2,%3}, [%4];"
                 : "=r"(r0), "=r"(r1), "=r"(r2), "=r"(r3) : "r"(addr));
}
__device__ __forceinline__ void ldsm_x4_t(uint32_t& r0, uint32_t& r1, uint32_t& r2,
                                          uint32_t& r3, uint32_t addr) {
    asm volatile("ldmatrix.sync.aligned.m8n8.x4.trans.shared.b16 {%0,%1,%2,%3}, [%4];"
                 : "=r"(r0), "=r"(r1), "=r"(r2), "=r"(r3) : "r"(addr));
}
__device__ __forceinline__ void mma16816(float* d, const uint32_t* a, const uint32_t* b) {
    asm volatile("mma.sync.aligned.m16n8k16.row.col.f32.f16.f16.f32 "
                 "{%0,%1,%2,%3}, {%4,%5,%6,%7}, {%8,%9}, {%0,%1,%2,%3};"
                 : "+f"(d[0]), "+f"(d[1]), "+f"(d[2]), "+f"(d[3])
                 : "r"(a[0]), "r"(a[1]), "r"(a[2]), "r"(a[3]), "r"(b[0]), "r"(b[1]));
}
__device__ __forceinline__ void cp16(uint32_t saddr, const void* gaddr) {
    asm volatile("cp.async.cg.shared.global [%0], [%1], 16;" :: "r"(saddr), "l"(gaddr));
}
__device__ __forceinline__ void cp_commit() {
    asm volatile("cp.async.commit_group;" ::: "memory");
}
__device__ __forceinline__ void cp_wait0() {
    asm volatile("cp.async.wait_group 0;" ::: "memory");
}

// ===================== wfuse: Wf = emb@W0 (fp32), bf = emb_b@W0 =====================
__global__ void wfuse_kernel(const float* __restrict__ embW, const float* __restrict__ embb,
                             const float* __restrict__ W0)
{
    __shared__ float row[H_];
    const int f = blockIdx.x, o = threadIdx.x;
    row[o] = (f < FIN_) ? embW[f * H_ + o] : embb[o];
    __syncthreads();
    float acc = 0.f;
#pragma unroll 8
    for (int h = 0; h < H_; h++) acc = fmaf(row[h], W0[h * H_ + o], acc);
    if (f < FIN_) g_wf16[f * H_ + o] = __float2half(acc);
    else          g_bf[o] = acc;
}

__global__ void prepw1_kernel(const float* __restrict__ W1)
{
    int i = blockIdx.x * 256 + threadIdx.x;
    g_w116[i] = __float2half(W1[i]);
}

// ===================== hgemm: C[16384,256] = A[16384,K] @ Bw[K,256] (+bias) =====
template <int KDIM, bool AFP32>
__global__ void __launch_bounds__(256, 2) hgemm_mma(
    const void* __restrict__ Araw, const __half* __restrict__ Bw,
    const float* __restrict__ bias, const float* __restrict__ a1v,
    const float* __restrict__ a2v,
    __half* __restrict__ out16, float* __restrict__ s1o, float* __restrict__ s2o)
{
    __shared__ __half As[2][64][40];
    __shared__ __half Bs[2][32][264];
    __shared__ float vb1[H_], vb2[H_], bb[H_];
    __shared__ float s1b[64], s2b[64];

    const int tid = threadIdx.x, wid = tid >> 5, lane = tid & 31;
    const int wm = wid >> 2, wn = wid & 3;
    const int row0 = blockIdx.x * 64;

    vb1[tid] = a1v[tid];
    vb2[tid] = a2v[tid];
    bb[tid]  = bias ? bias[tid] : 0.f;
    if (tid < 64) { s1b[tid] = 0.f; s2b[tid] = 0.f; }

    const uint32_t asu = smem_u32(&As[0][0][0]);
    const uint32_t bsu = smem_u32(&Bs[0][0][0]);
    constexpr uint32_t ASTG = 64 * 40 * 2;
    constexpr uint32_t BSTG = 32 * 264 * 2;

    float acc[2][8][4];
#pragma unroll
    for (int i = 0; i < 2; i++)
#pragma unroll
        for (int j = 0; j < 8; j++)
#pragma unroll
            for (int t = 0; t < 4; t++) acc[i][j][t] = 0.f;

    const int arow = tid >> 2, aseg = tid & 3;
    const int brow = tid >> 3, bseg = (tid & 7) * 32;

    float4 aF0, aF1;
    uint4  aPk;

    auto loadA = [&](int k0) {
        if (AFP32) {
            const float* A = (const float*)Araw;
            const float* p = A + (size_t)(row0 + arow) * KDIM + k0 + aseg * 8;
            aF0 = *(const float4*)p;
            aF1 = *(const float4*)(p + 4);
        } else {
            const __half* A = (const __half*)Araw;
            aPk = *(const uint4*)(A + (size_t)(row0 + arow) * KDIM + k0 + aseg * 8);
        }
    };
    auto stsA = [&](int st) {
        uint32_t dst = asu + st * ASTG + (arow * 40 + aseg * 8) * 2;
        if (AFP32) {
            __half2 h0 = __floats2half2_rn(aF0.x, aF0.y);
            __half2 h1 = __floats2half2_rn(aF0.z, aF0.w);
            __half2 h2 = __floats2half2_rn(aF1.x, aF1.y);
            __half2 h3 = __floats2half2_rn(aF1.z, aF1.w);
            asm volatile("st.shared.v4.b32 [%0], {%1,%2,%3,%4};" :: "r"(dst),
                         "r"(*(uint32_t*)&h0), "r"(*(uint32_t*)&h1),
                         "r"(*(uint32_t*)&h2), "r"(*(uint32_t*)&h3) : "memory");
        } else {
            asm volatile("st.shared.v4.b32 [%0], {%1,%2,%3,%4};" :: "r"(dst),
                         "r"(aPk.x), "r"(aPk.y), "r"(aPk.z), "r"(aPk.w) : "memory");
        }
    };
    auto cpB = [&](int k0, int st) {
        const __half* src = Bw + (size_t)(k0 + brow) * H_ + bseg;
        uint32_t dst = bsu + st * BSTG + (brow * 264 + bseg) * 2;
#pragma unroll
        for (int u = 0; u < 4; u++) cp16(dst + u * 16, src + u * 8);
        cp_commit();
    };
    auto compute = [&](int buf) {
        const uint32_t asb = asu + buf * ASTG;
        const uint32_t bsb = bsu + buf * BSTG;
#pragma unroll
        for (int ksi = 0; ksi < 2; ksi++) {
            const int ksl = ksi * 16;
            uint32_t af[2][4];
#pragma unroll
            for (int mf = 0; mf < 2; mf++) {
                int r = wm * 32 + mf * 16 + (lane & 15);
                int c = ksl + (lane >> 4) * 8;
                ldsm_x4(af[mf][0], af[mf][1], af[mf][2], af[mf][3], asb + (r * 40 + c) * 2);
            }
            uint32_t bf[8][2];
#pragma unroll
            for (int ng = 0; ng < 4; ng++) {
                int r = ksl + (lane & 15);
                int c = wn * 64 + ng * 16 + (lane >> 4) * 8;
                ldsm_x4_t(bf[ng * 2][0], bf[ng * 2][1], bf[ng * 2 + 1][0], bf[ng * 2 + 1][1],
                          bsb + (r * 264 + c) * 2);
            }
#pragma unroll
            for (int mf = 0; mf < 2; mf++)
#pragma unroll
                for (int nf = 0; nf < 8; nf++)
                    mma16816(acc[mf][nf], af[mf], bf[nf]);
        }
    };

    constexpr int NK = KDIM / 32;
    loadA(0);
    stsA(0);
    cpB(0, 0);
    loadA(32);
#pragma unroll
    for (int s = 0; s < NK; s++) {
        const int buf = s & 1;
        cp_wait0();
        __syncthreads();
        if (s + 1 < NK) {
            stsA(buf ^ 1);
            cpB((s + 1) * 32, buf ^ 1);
            if (s + 2 < NK) loadA((s + 2) * 32);
        }
        compute(buf);
    }

    // ---------------- epilogue ----------------
    const int r1 = lane >> 2, cq = (lane & 3) * 2;
#pragma unroll
    for (int mf = 0; mf < 2; mf++) {
#pragma unroll
        for (int rr = 0; rr < 2; rr++) {
            const int rloc = wm * 32 + mf * 16 + r1 + rr * 8;
            const int grow = row0 + rloc;
            float p1 = 0.f, p2 = 0.f;
#pragma unroll
            for (int nf = 0; nf < 8; nf++) {
                const int col = wn * 64 + nf * 8 + cq;
                float e0 = acc[mf][nf][rr * 2]     + bb[col];
                float e1 = acc[mf][nf][rr * 2 + 1] + bb[col + 1];
                p1 = fmaf(e0, vb1[col], fmaf(e1, vb1[col + 1], p1));
                p2 = fmaf(e0, vb2[col], fmaf(e1, vb2[col + 1], p2));
                ((__half2*)out16)[((size_t)grow * H_ + col) >> 1] = __floats2half2_rn(e0, e1);
            }
            p1 += __shfl_xor_sync(0xffffffffu, p1, 1);
            p1 += __shfl_xor_sync(0xffffffffu, p1, 2);
            p2 += __shfl_xor_sync(0xffffffffu, p2, 1);
            p2 += __shfl_xor_sync(0xffffffffu, p2, 2);
            if ((lane & 3) == 0) {
                atomicAdd(&s1b[rloc], p1);
                atomicAdd(&s2b[rloc], p2);
            }
        }
    }
    __syncthreads();
    if (tid < 64) { s1o[row0 + tid] = s1b[tid]; s2o[row0 + tid] = s2b[tid]; }
}

// ===================== stat: masked row-max (exact), write E fp16 + 1/l =========
// m_i = leaky(s1_i + max_{j in mask} s2_j)  == exact row max (leaky monotone).
// E[i][j] = mask ? exp(leaky(s1_i+s2_j) - m_i) : 0.  Degenerate row -> E=1, l=1024.
template <bool FIRST>
__global__ void __launch_bounds__(256) stat_kernel(
    const float* __restrict__ adj, const float* __restrict__ s1,
    const float* __restrict__ s2, float* __restrict__ grl, __half* __restrict__ E)
{
    __shared__ float s2s[N_];
    const int b = blockIdx.y, tid = threadIdx.x;
    const int wid = tid >> 5, lane = tid & 31;
    for (int i = tid; i < N_; i += 256) s2s[i] = s2[b * N_ + i];
    __syncthreads();

    const int row = b * N_ + blockIdx.x * 8 + wid;
    const float s1i = s1[row];

    uint32_t mw;                          // this lane's pair-interleaved mask word
    float mloc = -1e30f;

    if (FIRST) {
        const float2* ar = (const float2*)(adj + (size_t)row * N_);
#pragma unroll
        for (int g = 0; g < 16; g++) {
            float2 a = ar[g * 32 + lane];
            uint32_t b0 = __ballot_sync(0xffffffffu, a.x > 0.f);
            uint32_t b1 = __ballot_sync(0xffffffffu, a.y > 0.f);
            if ((lane >> 1) == g) mw = (lane & 1) ? b1 : b0;
            float2 sv = *(const float2*)&s2s[g * 64 + lane * 2];
            if (a.x > 0.f) mloc = fmaxf(mloc, sv.x);
            if (a.y > 0.f) mloc = fmaxf(mloc, sv.y);
        }
        g_mask[(size_t)row * 32 + lane] = mw;
    } else {
        mw = g_mask[(size_t)row * 32 + lane];
#pragma unroll
        for (int g = 0; g < 16; g++) {
            uint32_t w0 = __shfl_sync(0xffffffffu, mw, 2 * g);
            uint32_t w1 = __shfl_sync(0xffffffffu, mw, 2 * g + 1);
            float2 sv = *(const float2*)&s2s[g * 64 + lane * 2];
            if ((w0 >> lane) & 1u) mloc = fmaxf(mloc, sv.x);
            if ((w1 >> lane) & 1u) mloc = fmaxf(mloc, sv.y);
        }
    }
#pragma unroll
    for (int o = 16; o > 0; o >>= 1)
        mloc = fmaxf(mloc, __shfl_xor_sync(0xffffffffu, mloc, o));

    const bool deg = (mloc < -1e29f);
    const float xm = s1i + mloc;
    const float mhat = fmaxf(xm, 0.2f * xm);

    float l = 0.f;
    __half2* Erow = (__half2*)(E + (size_t)row * N_);
#pragma unroll
    for (int g = 0; g < 16; g++) {
        uint32_t w0 = __shfl_sync(0xffffffffu, mw, 2 * g);
        uint32_t w1 = __shfl_sync(0xffffffffu, mw, 2 * g + 1);
        float2 sv = *(const float2*)&s2s[g * 64 + lane * 2];
        float x0 = s1i + sv.x, x1 = s1i + sv.y;
        float e0 = ((w0 >> lane) & 1u) ? __expf(fmaxf(x0, 0.2f * x0) - mhat) : 0.f;
        float e1 = ((w1 >> lane) & 1u) ? __expf(fmaxf(x1, 0.2f * x1) - mhat) : 0.f;
        if (deg) { e0 = 1.f; e1 = 1.f; }
        Erow[g * 32 + lane] = __floats2half2_rn(e0, e1);
        l += e0 + e1;
    }
#pragma unroll
    for (int o = 16; o > 0; o >>= 1)
        l += __shfl_xor_sync(0xffffffffu, l, o);
    if (lane == 0) grl[row] = 1.f / l;
}

// ===================== attention: pure GEMM out = E @ h, scaled by rl ===========
__global__ void __launch_bounds__(256, 2) att_mma(
    const __half* __restrict__ E, const __half* __restrict__ h16,
    const float* __restrict__ rl,
    __half* __restrict__ out16, float* __restrict__ outf)
{
    __shared__ __half As[2][64][40];
    __shared__ __half Bs[2][32][264];

    const int tid = threadIdx.x, wid = tid >> 5, lane = tid & 31;
    const int wm = wid >> 2, wn = wid & 3;
    const int b = blockIdx.y, i0 = blockIdx.x * 64;

    const uint32_t asu = smem_u32(&As[0][0][0]);
    const uint32_t bsu = smem_u32(&Bs[0][0][0]);
    constexpr uint32_t ASTG = 64 * 40 * 2;
    constexpr uint32_t BSTG = 32 * 264 * 2;

    float acc[2][8][4];
#pragma unroll
    for (int i = 0; i < 2; i++)
#pragma unroll
        for (int j = 0; j < 8; j++)
#pragma unroll
            for (int t = 0; t < 4; t++) acc[i][j][t] = 0.f;

    const int arow = tid >> 2, aseg = tid & 3;
    const int brow = tid >> 3, bseg = (tid & 7) * 32;

    const __half* Erow = E + (size_t)(b * N_ + i0 + arow) * N_ + aseg * 8;
    const uint32_t adst = asu + (arow * 40 + aseg * 8) * 2;
    const uint32_t bdst = bsu + (brow * 264 + bseg) * 2;

    auto cpTiles = [&](int k0, int st) {
        cp16(adst + st * ASTG, Erow + k0);
        const __half* src = h16 + (size_t)(b * N_ + k0 + brow) * H_ + bseg;
        uint32_t d = bdst + st * BSTG;
#pragma unroll
        for (int u = 0; u < 4; u++) cp16(d + u * 16, src + u * 8);
        cp_commit();
    };
    auto compute = [&](int buf) {
        const uint32_t asb = asu + buf * ASTG;
        const uint32_t bsb = bsu + buf * BSTG;
#pragma unroll
        for (int ksi = 0; ksi < 2; ksi++) {
            const int ksl = ksi * 16;
            uint32_t af[2][4];
#pragma unroll
            for (int mf = 0; mf < 2; mf++) {
                int r = wm * 32 + mf * 16 + (lane & 15);
                int c = ksl + (lane >> 4) * 8;
                ldsm_x4(af[mf][0], af[mf][1], af[mf][2], af[mf][3], asb + (r * 40 + c) * 2);
            }
            uint32_t bf[8][2];
#pragma unroll
            for (int ng = 0; ng < 4; ng++) {
                int r = ksl + (lane & 15);
                int c = wn * 64 + ng * 16 + (lane >> 4) * 8;
                ldsm_x4_t(bf[ng * 2][0], bf[ng * 2][1], bf[ng * 2 + 1][0], bf[ng * 2 + 1][1],
                          bsb + (r * 264 + c) * 2);
            }
#pragma unroll
            for (int mf = 0; mf < 2; mf++)
#pragma unroll
                for (int nf = 0; nf < 8; nf++)
                    mma16816(acc[mf][nf], af[mf], bf[nf]);
        }
    };

    constexpr int NK = N_ / 32;   // 32
    cpTiles(0, 0);
    for (int s = 0; s < NK; s++) {
        const int buf = s & 1;
        cp_wait0();
        __syncthreads();
        if (s + 1 < NK) cpTiles((s + 1) * 32, buf ^ 1);
        compute(buf);
    }

    // ---------------- epilogue: scale by rl_i, relu, write ----------------
    const int r1 = lane >> 2, cq = (lane & 3) * 2;
#pragma unroll
    for (int mf = 0; mf < 2; mf++) {
#pragma unroll
        for (int rr = 0; rr < 2; rr++) {
            const int rloc = wm * 32 + mf * 16 + r1 + rr * 8;
            const int grow = b * N_ + i0 + rloc;
            const float scale = rl[grow];
#pragma unroll
            for (int nf = 0; nf < 8; nf++) {
                const int col = wn * 64 + nf * 8 + cq;
                float e0 = fmaxf(acc[mf][nf][rr * 2]     * scale, 0.f);
                float e1 = fmaxf(acc[mf][nf][rr * 2 + 1] * scale, 0.f);
                if (outf) {
                    float2 v = { e0, e1 };
                    *(float2*)(outf + (size_t)grow * H_ + col) = v;
                } else {
                    ((__half2*)out16)[((size_t)grow * H_ + col) >> 1] = __floats2half2_rn(e0, e1);
                }
            }
        }
    }
}

// ===================== pooling + MLP head =====================
__global__ void pool_partial(const float* __restrict__ x)
{
    const int b = blockIdx.y, ch = blockIdx.x, c = threadIdx.x;
    const float* p = x + (size_t)(b * N_ + ch * 128) * H_ + c;
    float s = 0.f, mx = -1e30f;
#pragma unroll 4
    for (int n = 0; n < 128; n++) {
        float v = p[(size_t)n * H_];
        s += v; mx = fmaxf(mx, v);
    }
    g_psum[(b * 8 + ch) * H_ + c] = s;
    g_pmax[(b * 8 + ch) * H_ + c] = mx;
}

__global__ void final_kernel(const float* __restrict__ W1, const float* __restrict__ b1,
                             const float* __restrict__ W2, const float* __restrict__ b2,
                             float* __restrict__ gout)
{
    __shared__ float gv[H_], g1[H_];
    const int b = blockIdx.x, c = threadIdx.x;
    float s = 0.f, mx = -1e30f;
#pragma unroll
    for (int ch = 0; ch < 8; ch++) {
        s += g_psum[(b * 8 + ch) * H_ + c];
        mx = fmaxf(mx, g_pmax[(b * 8 + ch) * H_ + c]);
    }
    gv[c] = s * (1.0f / N_) + mx;
    __syncthreads();
    float a = b1[c];
    for (int k = 0; k < H_; k++) a = fmaf(gv[k], W1[k * H_ + c], a);
    g1[c] = fmaxf(a, 0.f);
    __syncthreads();
    float a2 = b2[c];
    for (int k = 0; k < H_; k++) a2 = fmaf(g1[k], W2[k * H_ + c], a2);
    gout[b * H_ + c] = a2;
}

// ===================== launch =====================
extern "C" void kernel_launch(void* const* d_in, const int* in_sizes, int n_in,
                              void* d_out, int out_size)
{
    const float* nf   = (const float*)d_in[0];
    const float* adj  = (const float*)d_in[1];
    const float* embW = (const float*)d_in[2];
    const float* embb = (const float*)d_in[3];
    const float* W0   = (const float*)d_in[4];
    const float* a1_0 = (const float*)d_in[5];
    const float* a2_0 = (const float*)d_in[6];
    const float* W1   = (const float*)d_in[7];
    const float* a1_1 = (const float*)d_in[8];
    const float* a2_1 = (const float*)d_in[9];
    const float* gpW1 = (const float*)d_in[10];
    const float* gpb1 = (const float*)d_in[11];
    const float* gpW2 = (const float*)d_in[12];
    const float* gpb2 = (const float*)d_in[13];

    float* out  = (float*)d_out;
    float* outg = out + (size_t)B_ * N_ * H_;

    __half *pE, *px16b, *ph16, *pwf, *pw1;
    float *ps1, *ps2, *prl, *pbf;
    cudaGetSymbolAddress((void**)&pE,    g_E);
    cudaGetSymbolAddress((void**)&px16b, g_x16b);
    cudaGetSymbolAddress((void**)&ph16,  g_h16);
    cudaGetSymbolAddress((void**)&pwf,   g_wf16);
    cudaGetSymbolAddress((void**)&pw1,   g_w116);
    cudaGetSymbolAddress((void**)&pbf,   g_bf);
    cudaGetSymbolAddress((void**)&ps1,   g_s1);
    cudaGetSymbolAddress((void**)&ps2,   g_s2);
    cudaGetSymbolAddress((void**)&prl,   g_rl);

    const int M = B_ * N_;

    wfuse_kernel<<<FIN_ + 1, 256>>>(embW, embb, W0);
    prepw1_kernel<<<H_ * H_ / 256, 256>>>(W1);

    // ---- layer 1 (embed folded into Wf; mask built inside stat) ----
    hgemm_mma<FIN_, true><<<M / 64, 256>>>(nf, pwf, pbf, a1_0, a2_0, ph16, ps1, ps2);
    stat_kernel<true><<<dim3(N_ / 8, B_), 256>>>(adj, ps1, ps2, prl, pE);
    att_mma<<<dim3(N_ / 64, B_), 256>>>(pE, ph16, prl, px16b, nullptr);

    // ---- layer 2 ----
    hgemm_mma<H_, false><<<M / 64, 256>>>(px16b, pw1, nullptr, a1_1, a2_1, ph16, ps1, ps2);
    stat_kernel<false><<<dim3(N_ / 8, B_), 256>>>(nullptr, ps1, ps2, prl, pE);
    att_mma<<<dim3(N_ / 64, B_), 256>>>(pE, ph16, prl, nullptr, out);

    // ---- pooling + MLP head ----
    pool_partial<<<dim3(8, B_), 256>>>(out);
    final_kernel<<<B_, 256>>>(gpW1, gpb1, gpW2, gpb2, outg);
}

// round 8
// speedup vs baseline: 1.0564x; 1.0564x over previous
#include <cuda_runtime.h>
#include <cuda_fp16.h>
#include <cstdint>

#define B_ 16
#define N_ 1024
#define FIN_ 64
#define H_ 256

// ===================== scratch (static device globals) =====================
__device__ __half    g_E    [B_ * N_ * N_];   // unnormalized masked exp (fp16), 32MB
__device__ __half    g_x16b [B_ * N_ * H_];   // layer1 output (fp16)
__device__ __half    g_h16  [B_ * N_ * H_];   // h natural layout [b][j][c]
__device__ __half    g_wf16 [FIN_ * H_];      // fused emb@W0 (fp16)
__device__ float     g_bf   [H_];             // fused bias emb_b@W0
__device__ __half    g_w116 [H_ * H_];
__device__ uint32_t  g_mask [B_ * N_ * 32];   // word g: ballot of col g*32+lane
__device__ float     g_s1[B_ * N_], g_s2[B_ * N_], g_rl[B_ * N_];
__device__ float     g_psum[B_ * 8 * H_], g_pmax[B_ * 8 * H_];

// ===================== mma/ldmatrix/cp.async helpers (baseline PTX) ============
__device__ __forceinline__ uint32_t smem_u32(const void* p) {
    uint32_t a;
    asm("{ .reg .u64 t; cvta.to.shared.u64 t, %1; cvt.u32.u64 %0, t; }" : "=r"(a) : "l"(p));
    return a;
}
__device__ __forceinline__ void ldsm_x4(uint32_t& r0, uint32_t& r1, uint32_t& r2,
                                        uint32_t& r3, uint32_t addr) {
    asm volatile("ldmatrix.sync.aligned.m8n8.x4.shared.b16 {%0,%1,%2,%3}, [%4];"
                 : "=r"(r0), "=r"(r1), "=r"(r2), "=r"(r3) : "r"(addr));
}
__device__ __forceinline__ void ldsm_x4_t(uint32_t& r0, uint32_t& r1, uint32_t& r2,
                                          uint32_t& r3, uint32_t addr) {
    asm volatile("ldmatrix.sync.aligned.m8n8.x4.trans.shared.b16 {%0,%1,%2,%3}, [%4];"
                 : "=r"(r0), "=r"(r1), "=r"(r2), "=r"(r3) : "r"(addr));
}
__device__ __forceinline__ void mma16816(float* d, const uint32_t* a, const uint32_t* b) {
    asm volatile("mma.sync.aligned.m16n8k16.row.col.f32.f16.f16.f32 "
                 "{%0,%1,%2,%3}, {%4,%5,%6,%7}, {%8,%9}, {%0,%1,%2,%3};"
                 : "+f"(d[0]), "+f"(d[1]), "+f"(d[2]), "+f"(d[3])
                 : "r"(a[0]), "r"(a[1]), "r"(a[2]), "r"(a[3]), "r"(b[0]), "r"(b[1]));
}
__device__ __forceinline__ void cp16(uint32_t saddr, const void* gaddr) {
    asm volatile("cp.async.cg.shared.global [%0], [%1], 16;" :: "r"(saddr), "l"(gaddr));
}
__device__ __forceinline__ void cp_commit() {
    asm volatile("cp.async.commit_group;" ::: "memory");
}
__device__ __forceinline__ void cp_wait0() {
    asm volatile("cp.async.wait_group 0;" ::: "memory");
}
__device__ __forceinline__ void cp_wait2() {
    asm volatile("cp.async.wait_group 2;" ::: "memory");
}

// tile geometry shared by the MMA kernels
static constexpr uint32_t ASTG = 64 * 40 * 2;    // 5120 B per A stage
static constexpr uint32_t BSTG = 32 * 264 * 2;   // 16896 B per B stage
static constexpr uint32_t STG4_BYTES = 4 * (ASTG + BSTG);   // 88064

// ===================== wfuse: Wf = emb@W0 (fp32), bf = emb_b@W0 =====================
__global__ void wfuse_kernel(const float* __restrict__ embW, const float* __restrict__ embb,
                             const float* __restrict__ W0)
{
    __shared__ float row[H_];
    const int f = blockIdx.x, o = threadIdx.x;
    row[o] = (f < FIN_) ? embW[f * H_ + o] : embb[o];
    __syncthreads();
    float acc = 0.f;
#pragma unroll 8
    for (int h = 0; h < H_; h++) acc = fmaf(row[h], W0[h * H_ + o], acc);
    if (f < FIN_) g_wf16[f * H_ + o] = __float2half(acc);
    else          g_bf[o] = acc;
}

__global__ void prepw1_kernel(const float* __restrict__ W1)
{
    int i = blockIdx.x * 256 + threadIdx.x;
    g_w116[i] = __float2half(W1[i]);
}

// ===================== shared epilogue for h-GEMMs =====================
// (writes h fp16 + s1/s2 dot reductions)
#define HGEMM_EPILOGUE()                                                          \
    const int r1 = lane >> 2, cq = (lane & 3) * 2;                                \
    _Pragma("unroll")                                                             \
    for (int mf = 0; mf < 2; mf++) {                                              \
        _Pragma("unroll")                                                         \
        for (int rr = 0; rr < 2; rr++) {                                          \
            const int rloc = wm * 32 + mf * 16 + r1 + rr * 8;                     \
            const int grow = row0 + rloc;                                         \
            float p1 = 0.f, p2 = 0.f;                                             \
            _Pragma("unroll")                                                     \
            for (int nf = 0; nf < 8; nf++) {                                      \
                const int col = wn * 64 + nf * 8 + cq;                            \
                float e0 = acc[mf][nf][rr * 2]     + bb[col];                     \
                float e1 = acc[mf][nf][rr * 2 + 1] + bb[col + 1];                 \
                p1 = fmaf(e0, vb1[col], fmaf(e1, vb1[col + 1], p1));              \
                p2 = fmaf(e0, vb2[col], fmaf(e1, vb2[col + 1], p2));              \
                ((__half2*)out16)[((size_t)grow * H_ + col) >> 1] =               \
                    __floats2half2_rn(e0, e1);                                    \
            }                                                                     \
            p1 += __shfl_xor_sync(0xffffffffu, p1, 1);                            \
            p1 += __shfl_xor_sync(0xffffffffu, p1, 2);                            \
            p2 += __shfl_xor_sync(0xffffffffu, p2, 1);                            \
            p2 += __shfl_xor_sync(0xffffffffu, p2, 2);                            \
            if ((lane & 3) == 0) {                                                \
                atomicAdd(&s1b[rloc], p1);                                        \
                atomicAdd(&s2b[rloc], p2);                                        \
            }                                                                     \
        }                                                                         \
    }                                                                             \
    __syncthreads();                                                              \
    if (tid < 64) { s1o[row0 + tid] = s1b[tid]; s2o[row0 + tid] = s2b[tid]; }

// shared compute step over one 64x32x256 stage
#define MMA_COMPUTE(asb, bsb)                                                     \
    _Pragma("unroll")                                                             \
    for (int ksi = 0; ksi < 2; ksi++) {                                           \
        const int ksl = ksi * 16;                                                 \
        uint32_t af[2][4];                                                        \
        _Pragma("unroll")                                                         \
        for (int mf = 0; mf < 2; mf++) {                                          \
            int r = wm * 32 + mf * 16 + (lane & 15);                              \
            int c = ksl + (lane >> 4) * 8;                                        \
            ldsm_x4(af[mf][0], af[mf][1], af[mf][2], af[mf][3],                   \
                    (asb) + (r * 40 + c) * 2);                                    \
        }                                                                         \
        uint32_t bf[8][2];                                                        \
        _Pragma("unroll")                                                         \
        for (int ng = 0; ng < 4; ng++) {                                          \
            int r = ksl + (lane & 15);                                            \
            int c = wn * 64 + ng * 16 + (lane >> 4) * 8;                          \
            ldsm_x4_t(bf[ng * 2][0], bf[ng * 2][1],                               \
                      bf[ng * 2 + 1][0], bf[ng * 2 + 1][1],                       \
                      (bsb) + (r * 264 + c) * 2);                                 \
        }                                                                         \
        _Pragma("unroll")                                                         \
        for (int mf = 0; mf < 2; mf++)                                            \
            _Pragma("unroll")                                                     \
            for (int nf = 0; nf < 8; nf++)                                        \
                mma16816(acc[mf][nf], af[mf], bf[nf]);                            \
    }

// ===================== layer-1 h-GEMM (fp32 A, KDIM=64, 2-stage) ================
__global__ void __launch_bounds__(256, 2) hgemm_l1(
    const float* __restrict__ A, const __half* __restrict__ Bw,
    const float* __restrict__ bias, const float* __restrict__ a1v,
    const float* __restrict__ a2v,
    __half* __restrict__ out16, float* __restrict__ s1o, float* __restrict__ s2o)
{
    __shared__ __half As[2][64][40];
    __shared__ __half Bs[2][32][264];
    __shared__ float vb1[H_], vb2[H_], bb[H_];
    __shared__ float s1b[64], s2b[64];

    const int tid = threadIdx.x, wid = tid >> 5, lane = tid & 31;
    const int wm = wid >> 2, wn = wid & 3;
    const int row0 = blockIdx.x * 64;

    vb1[tid] = a1v[tid];
    vb2[tid] = a2v[tid];
    bb[tid]  = bias[tid];
    if (tid < 64) { s1b[tid] = 0.f; s2b[tid] = 0.f; }

    const uint32_t asu = smem_u32(&As[0][0][0]);
    const uint32_t bsu = smem_u32(&Bs[0][0][0]);

    float acc[2][8][4];
#pragma unroll
    for (int i = 0; i < 2; i++)
#pragma unroll
        for (int j = 0; j < 8; j++)
#pragma unroll
            for (int t = 0; t < 4; t++) acc[i][j][t] = 0.f;

    const int arow = tid >> 2, aseg = tid & 3;
    const int brow = tid >> 3, bseg = (tid & 7) * 32;

    // prologue: both K-chunks (KDIM=64 -> NK=2)
#pragma unroll
    for (int s = 0; s < 2; s++) {
        const float* p = A + (size_t)(row0 + arow) * FIN_ + s * 32 + aseg * 8;
        float4 aF0 = *(const float4*)p;
        float4 aF1 = *(const float4*)(p + 4);
        __half2 h0 = __floats2half2_rn(aF0.x, aF0.y);
        __half2 h1 = __floats2half2_rn(aF0.z, aF0.w);
        __half2 h2 = __floats2half2_rn(aF1.x, aF1.y);
        __half2 h3 = __floats2half2_rn(aF1.z, aF1.w);
        uint32_t dst = asu + s * ASTG + (arow * 40 + aseg * 8) * 2;
        asm volatile("st.shared.v4.b32 [%0], {%1,%2,%3,%4};" :: "r"(dst),
                     "r"(*(uint32_t*)&h0), "r"(*(uint32_t*)&h1),
                     "r"(*(uint32_t*)&h2), "r"(*(uint32_t*)&h3) : "memory");
        const __half* src = Bw + (size_t)(s * 32 + brow) * H_ + bseg;
        uint32_t d = bsu + s * BSTG + (brow * 264 + bseg) * 2;
#pragma unroll
        for (int u = 0; u < 4; u++) cp16(d + u * 16, src + u * 8);
    }
    cp_commit();
    cp_wait0();
    __syncthreads();
#pragma unroll
    for (int s = 0; s < 2; s++) {
        const uint32_t asb = asu + s * ASTG;
        const uint32_t bsb = bsu + s * BSTG;
        MMA_COMPUTE(asb, bsb)
    }
    HGEMM_EPILOGUE()
}

// ===================== layer-2 h-GEMM (fp16 A, KDIM=256, 4-stage cp.async) ======
__global__ void __launch_bounds__(256, 2) hgemm_l2(
    const __half* __restrict__ A, const __half* __restrict__ Bw,
    const float* __restrict__ a1v, const float* __restrict__ a2v,
    __half* __restrict__ out16, float* __restrict__ s1o, float* __restrict__ s2o)
{
    extern __shared__ char dsm[];
    __shared__ float vb1[H_], vb2[H_], bb[H_];
    __shared__ float s1b[64], s2b[64];

    const int tid = threadIdx.x, wid = tid >> 5, lane = tid & 31;
    const int wm = wid >> 2, wn = wid & 3;
    const int row0 = blockIdx.x * 64;

    vb1[tid] = a1v[tid];
    vb2[tid] = a2v[tid];
    bb[tid]  = 0.f;
    if (tid < 64) { s1b[tid] = 0.f; s2b[tid] = 0.f; }
    __syncthreads();

    const uint32_t asu = smem_u32(dsm);
    const uint32_t bsu = asu + 4 * ASTG;

    float acc[2][8][4];
#pragma unroll
    for (int i = 0; i < 2; i++)
#pragma unroll
        for (int j = 0; j < 8; j++)
#pragma unroll
            for (int t = 0; t < 4; t++) acc[i][j][t] = 0.f;

    const int arow = tid >> 2, aseg = tid & 3;
    const int brow = tid >> 3, bseg = (tid & 7) * 32;
    const __half* Arow = A + (size_t)(row0 + arow) * H_ + aseg * 8;
    const uint32_t adst = asu + (arow * 40 + aseg * 8) * 2;
    const uint32_t bdst = bsu + (brow * 264 + bseg) * 2;

    auto cpTiles = [&](int s, int st) {
        cp16(adst + st * ASTG, Arow + s * 32);
        const __half* src = Bw + (size_t)(s * 32 + brow) * H_ + bseg;
        uint32_t d = bdst + st * BSTG;
#pragma unroll
        for (int u = 0; u < 4; u++) cp16(d + u * 16, src + u * 8);
        cp_commit();
    };

    constexpr int NK = H_ / 32;   // 8
    cpTiles(0, 0); cpTiles(1, 1); cpTiles(2, 2);
#pragma unroll
    for (int s = 0; s < NK; s++) {
        cp_wait2();
        __syncthreads();
        if (s + 3 < NK) cpTiles(s + 3, (s + 3) & 3);
        const uint32_t asb = asu + (s & 3) * ASTG;
        const uint32_t bsb = bsu + (s & 3) * BSTG;
        MMA_COMPUTE(asb, bsb)
    }
    HGEMM_EPILOGUE()
}

// ===================== stat: streaming, lane-owned mask bits =====================
// m_i = leaky(s1_i + max_{j in mask} s2_j) == exact masked row max (leaky monotone)
// E[i][j] = mask ? exp(leaky(s1_i+s2_j) - m_i) : 0;  degenerate row -> E=1, l=1024
template <bool FIRST>
__global__ void __launch_bounds__(256) stat_kernel(
    const float* __restrict__ adj, const float* __restrict__ s1,
    const float* __restrict__ s2, float* __restrict__ grl, __half* __restrict__ E)
{
    __shared__ float s2s[N_];
    const int b = blockIdx.y, tid = threadIdx.x;
    const int wid = tid >> 5, lane = tid & 31;
    for (int i = tid; i < N_; i += 256) s2s[i] = s2[b * N_ + i];
    __syncthreads();

    const int row = b * N_ + blockIdx.x * 8 + wid;
    const float s1i = s1[row];

    uint32_t mymask = 0;      // bit g = own predicate for column g*32+lane
    float mloc = -1e30f;

    if (FIRST) {
        const float* ar = adj + (size_t)row * N_;
        uint32_t wreg = 0;
#pragma unroll
        for (int g = 0; g < 32; g++) {
            float a = ar[g * 32 + lane];
            bool pred = (a > 0.f);
            uint32_t w = __ballot_sync(0xffffffffu, pred);
            if (lane == g) wreg = w;
            if (pred) {
                mymask |= (1u << g);
                mloc = fmaxf(mloc, s2s[g * 32 + lane]);
            }
        }
        g_mask[(size_t)row * 32 + lane] = wreg;
    } else {
        uint32_t wreg = g_mask[(size_t)row * 32 + lane];
#pragma unroll
        for (int g = 0; g < 32; g++) {
            uint32_t w = __shfl_sync(0xffffffffu, wreg, g);
            if ((w >> lane) & 1u) {
                mymask |= (1u << g);
                mloc = fmaxf(mloc, s2s[g * 32 + lane]);
            }
        }
    }
#pragma unroll
    for (int o = 16; o > 0; o >>= 1)
        mloc = fmaxf(mloc, __shfl_xor_sync(0xffffffffu, mloc, o));

    const bool deg = (mloc < -1e29f);
    const float xm = s1i + mloc;
    const float mhat = fmaxf(xm, 0.2f * xm);

    float l = 0.f;
    __half* Erow = E + (size_t)row * N_;
#pragma unroll
    for (int g = 0; g < 32; g++) {
        float x = s1i + s2s[g * 32 + lane];
        float e = ((mymask >> g) & 1u) ? __expf(fmaxf(x, 0.2f * x) - mhat) : 0.f;
        if (deg) e = 1.f;
        Erow[g * 32 + lane] = __float2half(e);
        l += e;
    }
#pragma unroll
    for (int o = 16; o > 0; o >>= 1)
        l += __shfl_xor_sync(0xffffffffu, l, o);
    if (lane == 0) grl[row] = 1.f / l;
}

// ===================== attention: pure GEMM out = E @ h (4-stage) ===============
__global__ void __launch_bounds__(256, 2) att_mma(
    const __half* __restrict__ E, const __half* __restrict__ h16,
    const float* __restrict__ rl,
    __half* __restrict__ out16, float* __restrict__ outf)
{
    extern __shared__ char dsm[];
    const int tid = threadIdx.x, wid = tid >> 5, lane = tid & 31;
    const int wm = wid >> 2, wn = wid & 3;
    const int b = blockIdx.y, i0 = blockIdx.x * 64;

    const uint32_t asu = smem_u32(dsm);
    const uint32_t bsu = asu + 4 * ASTG;

    float acc[2][8][4];
#pragma unroll
    for (int i = 0; i < 2; i++)
#pragma unroll
        for (int j = 0; j < 8; j++)
#pragma unroll
            for (int t = 0; t < 4; t++) acc[i][j][t] = 0.f;

    const int arow = tid >> 2, aseg = tid & 3;
    const int brow = tid >> 3, bseg = (tid & 7) * 32;

    const __half* Erow = E + (size_t)(b * N_ + i0 + arow) * N_ + aseg * 8;
    const uint32_t adst = asu + (arow * 40 + aseg * 8) * 2;
    const uint32_t bdst = bsu + (brow * 264 + bseg) * 2;

    auto cpTiles = [&](int s, int st) {
        cp16(adst + st * ASTG, Erow + s * 32);
        const __half* src = h16 + (size_t)(b * N_ + s * 32 + brow) * H_ + bseg;
        uint32_t d = bdst + st * BSTG;
#pragma unroll
        for (int u = 0; u < 4; u++) cp16(d + u * 16, src + u * 8);
        cp_commit();
    };

    constexpr int NK = N_ / 32;   // 32
    cpTiles(0, 0); cpTiles(1, 1); cpTiles(2, 2);
    for (int s = 0; s < NK; s++) {
        cp_wait2();
        __syncthreads();
        if (s + 3 < NK) cpTiles(s + 3, (s + 3) & 3);
        const uint32_t asb = asu + (s & 3) * ASTG;
        const uint32_t bsb = bsu + (s & 3) * BSTG;
        MMA_COMPUTE(asb, bsb)
    }

    // ---------------- epilogue: scale by rl_i, relu, write ----------------
    const int r1 = lane >> 2, cq = (lane & 3) * 2;
#pragma unroll
    for (int mf = 0; mf < 2; mf++) {
#pragma unroll
        for (int rr = 0; rr < 2; rr++) {
            const int rloc = wm * 32 + mf * 16 + r1 + rr * 8;
            const int grow = b * N_ + i0 + rloc;
            const float scale = rl[grow];
#pragma unroll
            for (int nf = 0; nf < 8; nf++) {
                const int col = wn * 64 + nf * 8 + cq;
                float e0 = fmaxf(acc[mf][nf][rr * 2]     * scale, 0.f);
                float e1 = fmaxf(acc[mf][nf][rr * 2 + 1] * scale, 0.f);
                if (outf) {
                    float2 v = { e0, e1 };
                    *(float2*)(outf + (size_t)grow * H_ + col) = v;
                } else {
                    ((__half2*)out16)[((size_t)grow * H_ + col) >> 1] = __floats2half2_rn(e0, e1);
                }
            }
        }
    }
}

// ===================== pooling + MLP head =====================
__global__ void pool_partial(const float* __restrict__ x)
{
    const int b = blockIdx.y, ch = blockIdx.x, c = threadIdx.x;
    const float* p = x + (size_t)(b * N_ + ch * 128) * H_ + c;
    float s = 0.f, mx = -1e30f;
#pragma unroll 4
    for (int n = 0; n < 128; n++) {
        float v = p[(size_t)n * H_];
        s += v; mx = fmaxf(mx, v);
    }
    g_psum[(b * 8 + ch) * H_ + c] = s;
    g_pmax[(b * 8 + ch) * H_ + c] = mx;
}

__global__ void final_kernel(const float* __restrict__ W1, const float* __restrict__ b1,
                             const float* __restrict__ W2, const float* __restrict__ b2,
                             float* __restrict__ gout)
{
    __shared__ float gv[H_], g1[H_];
    const int b = blockIdx.x, c = threadIdx.x;
    float s = 0.f, mx = -1e30f;
#pragma unroll
    for (int ch = 0; ch < 8; ch++) {
        s += g_psum[(b * 8 + ch) * H_ + c];
        mx = fmaxf(mx, g_pmax[(b * 8 + ch) * H_ + c]);
    }
    gv[c] = s * (1.0f / N_) + mx;
    __syncthreads();
    float a = b1[c];
    for (int k = 0; k < H_; k++) a = fmaf(gv[k], W1[k * H_ + c], a);
    g1[c] = fmaxf(a, 0.f);
    __syncthreads();
    float a2 = b2[c];
    for (int k = 0; k < H_; k++) a2 = fmaf(g1[k], W2[k * H_ + c], a2);
    gout[b * H_ + c] = a2;
}

// ===================== launch =====================
extern "C" void kernel_launch(void* const* d_in, const int* in_sizes, int n_in,
                              void* d_out, int out_size)
{
    const float* nf   = (const float*)d_in[0];
    const float* adj  = (const float*)d_in[1];
    const float* embW = (const float*)d_in[2];
    const float* embb = (const float*)d_in[3];
    const float* W0   = (const float*)d_in[4];
    const float* a1_0 = (const float*)d_in[5];
    const float* a2_0 = (const float*)d_in[6];
    const float* W1   = (const float*)d_in[7];
    const float* a1_1 = (const float*)d_in[8];
    const float* a2_1 = (const float*)d_in[9];
    const float* gpW1 = (const float*)d_in[10];
    const float* gpb1 = (const float*)d_in[11];
    const float* gpW2 = (const float*)d_in[12];
    const float* gpb2 = (const float*)d_in[13];

    float* out  = (float*)d_out;
    float* outg = out + (size_t)B_ * N_ * H_;

    __half *pE, *px16b, *ph16, *pwf, *pw1;
    float *ps1, *ps2, *prl, *pbf;
    cudaGetSymbolAddress((void**)&pE,    g_E);
    cudaGetSymbolAddress((void**)&px16b, g_x16b);
    cudaGetSymbolAddress((void**)&ph16,  g_h16);
    cudaGetSymbolAddress((void**)&pwf,   g_wf16);
    cudaGetSymbolAddress((void**)&pw1,   g_w116);
    cudaGetSymbolAddress((void**)&pbf,   g_bf);
    cudaGetSymbolAddress((void**)&ps1,   g_s1);
    cudaGetSymbolAddress((void**)&ps2,   g_s2);
    cudaGetSymbolAddress((void**)&prl,   g_rl);

    static bool attr_done = false;
    if (!attr_done) {
        cudaFuncSetAttribute(hgemm_l2, cudaFuncAttributeMaxDynamicSharedMemorySize, STG4_BYTES);
        cudaFuncSetAttribute(att_mma,  cudaFuncAttributeMaxDynamicSharedMemorySize, STG4_BYTES);
        attr_done = true;
    }

    const int M = B_ * N_;

    wfuse_kernel<<<FIN_ + 1, 256>>>(embW, embb, W0);
    prepw1_kernel<<<H_ * H_ / 256, 256>>>(W1);

    // ---- layer 1 (embed folded into Wf; mask built inside stat) ----
    hgemm_l1<<<M / 64, 256>>>(nf, pwf, pbf, a1_0, a2_0, ph16, ps1, ps2);
    stat_kernel<true><<<dim3(N_ / 8, B_), 256>>>(adj, ps1, ps2, prl, pE);
    att_mma<<<dim3(N_ / 64, B_), 256, STG4_BYTES>>>(pE, ph16, prl, px16b, nullptr);

    // ---- layer 2 ----
    hgemm_l2<<<M / 64, 256, STG4_BYTES>>>(px16b, pw1, a1_1, a2_1, ph16, ps1, ps2);
    stat_kernel<false><<<dim3(N_ / 8, B_), 256>>>(nullptr, ps1, ps2, prl, pE);
    att_mma<<<dim3(N_ / 64, B_), 256, STG4_BYTES>>>(pE, ph16, prl, nullptr, out);

    // ---- pooling + MLP head ----
    pool_partial<<<dim3(8, B_), 256>>>(out);
    final_kernel<<<B_, 256>>>(gpW1, gpb1, gpW2, gpb2, outg);
}

// round 12
// speedup vs baseline: 1.0785x; 1.0209x over previous
#include <cuda_runtime.h>
#include <cuda_fp16.h>
#include <cstdint>

#define B_ 16
#define N_ 1024
#define FIN_ 64
#define H_ 256

// ===================== scratch (static device globals) =====================
__device__ __half    g_E    [B_ * N_ * N_];   // unnormalized masked exp (fp16), 32MB
__device__ __half    g_x16b [B_ * N_ * H_];   // layer1 output (fp16)
__device__ __half    g_h16  [B_ * N_ * H_];   // h natural layout [b][j][c]
__device__ __half    g_wf16 [FIN_ * H_];      // fused emb@W0 (fp16)
__device__ float     g_bf   [H_];             // fused bias emb_b@W0
__device__ __half    g_w116 [H_ * H_];
__device__ uint32_t  g_mask [B_ * N_ * 32];   // lane-owned: word lane, bit g*4+t <-> col g*128+lane*4+t
__device__ float     g_s1[B_ * N_], g_s2[B_ * N_], g_rl[B_ * N_];
__device__ float     g_psum[B_ * 8 * H_], g_pmax[B_ * 8 * H_];

// ===================== mma/ldmatrix/cp.async helpers (baseline PTX) ============
__device__ __forceinline__ uint32_t smem_u32(const void* p) {
    uint32_t a;
    asm("{ .reg .u64 t; cvta.to.shared.u64 t, %1; cvt.u32.u64 %0, t; }" : "=r"(a) : "l"(p));
    return a;
}
__device__ __forceinline__ void ldsm_x4(uint32_t& r0, uint32_t& r1, uint32_t& r2,
                                        uint32_t& r3, uint32_t addr) {
    asm volatile("ldmatrix.sync.aligned.m8n8.x4.shared.b16 {%0,%1,%2,%3}, [%4];"
                 : "=r"(r0), "=r"(r1), "=r"(r2), "=r"(r3) : "r"(addr));
}
__device__ __forceinline__ void ldsm_x4_t(uint32_t& r0, uint32_t& r1, uint32_t& r2,
                                          uint32_t& r3, uint32_t addr) {
    asm volatile("ldmatrix.sync.aligned.m8n8.x4.trans.shared.b16 {%0,%1,%2,%3}, [%4];"
                 : "=r"(r0), "=r"(r1), "=r"(r2), "=r"(r3) : "r"(addr));
}
__device__ __forceinline__ void mma16816(float* d, const uint32_t* a, const uint32_t* b) {
    asm volatile("mma.sync.aligned.m16n8k16.row.col.f32.f16.f16.f32 "
                 "{%0,%1,%2,%3}, {%4,%5,%6,%7}, {%8,%9}, {%0,%1,%2,%3};"
                 : "+f"(d[0]), "+f"(d[1]), "+f"(d[2]), "+f"(d[3])
                 : "r"(a[0]), "r"(a[1]), "r"(a[2]), "r"(a[3]), "r"(b[0]), "r"(b[1]));
}
__device__ __forceinline__ void cp16(uint32_t saddr, const void* gaddr) {
    asm volatile("cp.async.cg.shared.global [%0], [%1], 16;" :: "r"(saddr), "l"(gaddr));
}
__device__ __forceinline__ void cp_commit() {
    asm volatile("cp.async.commit_group;" ::: "memory");
}
__device__ __forceinline__ void cp_wait0() {
    asm volatile("cp.async.wait_group 0;" ::: "memory");
}
__device__ __forceinline__ void cp_wait2() {
    asm volatile("cp.async.wait_group 2;" ::: "memory");
}

// tile geometry shared by the MMA kernels
static constexpr uint32_t ASTG = 64 * 40 * 2;    // 5120 B per A stage
static constexpr uint32_t BSTG = 32 * 264 * 2;   // 16896 B per B stage
static constexpr uint32_t STG4_BYTES = 4 * (ASTG + BSTG);   // 88064

// ===================== prep: Wf = emb@W0, bf = emb_b@W0, W1 fp16 ==============
__global__ void prep_kernel(const float* __restrict__ embW, const float* __restrict__ embb,
                            const float* __restrict__ W0, const float* __restrict__ W1)
{
    if (blockIdx.x < FIN_ + 1) {
        __shared__ float row[H_];
        const int f = blockIdx.x, o = threadIdx.x;
        row[o] = (f < FIN_) ? embW[f * H_ + o] : embb[o];
        __syncthreads();
        float acc = 0.f;
#pragma unroll 8
        for (int h = 0; h < H_; h++) acc = fmaf(row[h], W0[h * H_ + o], acc);
        if (f < FIN_) g_wf16[f * H_ + o] = __float2half(acc);
        else          g_bf[o] = acc;
    } else {
        int i = (blockIdx.x - (FIN_ + 1)) * 256 + threadIdx.x;
        g_w116[i] = __float2half(W1[i]);
    }
}

// ===================== shared epilogue for h-GEMMs =====================
#define HGEMM_EPILOGUE()                                                          \
    const int r1 = lane >> 2, cq = (lane & 3) * 2;                                \
    _Pragma("unroll")                                                             \
    for (int mf = 0; mf < 2; mf++) {                                              \
        _Pragma("unroll")                                                         \
        for (int rr = 0; rr < 2; rr++) {                                          \
            const int rloc = wm * 32 + mf * 16 + r1 + rr * 8;                     \
            const int grow = row0 + rloc;                                         \
            float p1 = 0.f, p2 = 0.f;                                             \
            _Pragma("unroll")                                                     \
            for (int nf = 0; nf < 8; nf++) {                                      \
                const int col = wn * 64 + nf * 8 + cq;                            \
                float e0 = acc[mf][nf][rr * 2]     + bb[col];                     \
                float e1 = acc[mf][nf][rr * 2 + 1] + bb[col + 1];                 \
                p1 = fmaf(e0, vb1[col], fmaf(e1, vb1[col + 1], p1));              \
                p2 = fmaf(e0, vb2[col], fmaf(e1, vb2[col + 1], p2));              \
                ((__half2*)out16)[((size_t)grow * H_ + col) >> 1] =               \
                    __floats2half2_rn(e0, e1);                                    \
            }                                                                     \
            p1 += __shfl_xor_sync(0xffffffffu, p1, 1);                            \
            p1 += __shfl_xor_sync(0xffffffffu, p1, 2);                            \
            p2 += __shfl_xor_sync(0xffffffffu, p2, 1);                            \
            p2 += __shfl_xor_sync(0xffffffffu, p2, 2);                            \
            if ((lane & 3) == 0) {                                                \
                atomicAdd(&s1b[rloc], p1);                                        \
                atomicAdd(&s2b[rloc], p2);                                        \
            }                                                                     \
        }                                                                         \
    }                                                                             \
    __syncthreads();                                                              \
    if (tid < 64) { s1o[row0 + tid] = s1b[tid]; s2o[row0 + tid] = s2b[tid]; }

#define MMA_COMPUTE(asb, bsb)                                                     \
    _Pragma("unroll")                                                             \
    for (int ksi = 0; ksi < 2; ksi++) {                                           \
        const int ksl = ksi * 16;                                                 \
        uint32_t af[2][4];                                                        \
        _Pragma("unroll")                                                         \
        for (int mf = 0; mf < 2; mf++) {                                          \
            int r = wm * 32 + mf * 16 + (lane & 15);                              \
            int c = ksl + (lane >> 4) * 8;                                        \
            ldsm_x4(af[mf][0], af[mf][1], af[mf][2], af[mf][3],                   \
                    (asb) + (r * 40 + c) * 2);                                    \
        }                                                                         \
        uint32_t bf[8][2];                                                        \
        _Pragma("unroll")                                                         \
        for (int ng = 0; ng < 4; ng++) {                                          \
            int r = ksl + (lane & 15);                                            \
            int c = wn * 64 + ng * 16 + (lane >> 4) * 8;                          \
            ldsm_x4_t(bf[ng * 2][0], bf[ng * 2][1],                               \
                      bf[ng * 2 + 1][0], bf[ng * 2 + 1][1],                       \
                      (bsb) + (r * 264 + c) * 2);                                 \
        }                                                                         \
        _Pragma("unroll")                                                         \
        for (int mf = 0; mf < 2; mf++)                                            \
            _Pragma("unroll")                                                     \
            for (int nf = 0; nf < 8; nf++)                                        \
                mma16816(acc[mf][nf], af[mf], bf[nf]);                            \
    }

// ===================== layer-1 h-GEMM (fp32 A, KDIM=64, 2-stage) ================
__global__ void __launch_bounds__(256, 2) hgemm_l1(
    const float* __restrict__ A, const __half* __restrict__ Bw,
    const float* __restrict__ bias, const float* __restrict__ a1v,
    const float* __restrict__ a2v,
    __half* __restrict__ out16, float* __restrict__ s1o, float* __restrict__ s2o)
{
    __shared__ __half As[2][64][40];
    __shared__ __half Bs[2][32][264];
    __shared__ float vb1[H_], vb2[H_], bb[H_];
    __shared__ float s1b[64], s2b[64];

    const int tid = threadIdx.x, wid = tid >> 5, lane = tid & 31;
    const int wm = wid >> 2, wn = wid & 3;
    const int row0 = blockIdx.x * 64;

    vb1[tid] = a1v[tid];
    vb2[tid] = a2v[tid];
    bb[tid]  = bias[tid];
    if (tid < 64) { s1b[tid] = 0.f; s2b[tid] = 0.f; }

    const uint32_t asu = smem_u32(&As[0][0][0]);
    const uint32_t bsu = smem_u32(&Bs[0][0][0]);

    float acc[2][8][4];
#pragma unroll
    for (int i = 0; i < 2; i++)
#pragma unroll
        for (int j = 0; j < 8; j++)
#pragma unroll
            for (int t = 0; t < 4; t++) acc[i][j][t] = 0.f;

    const int arow = tid >> 2, aseg = tid & 3;
    const int brow = tid >> 3, bseg = (tid & 7) * 32;

#pragma unroll
    for (int s = 0; s < 2; s++) {
        const float* p = A + (size_t)(row0 + arow) * FIN_ + s * 32 + aseg * 8;
        float4 aF0 = *(const float4*)p;
        float4 aF1 = *(const float4*)(p + 4);
        __half2 h0 = __floats2half2_rn(aF0.x, aF0.y);
        __half2 h1 = __floats2half2_rn(aF0.z, aF0.w);
        __half2 h2 = __floats2half2_rn(aF1.x, aF1.y);
        __half2 h3 = __floats2half2_rn(aF1.z, aF1.w);
        uint32_t dst = asu + s * ASTG + (arow * 40 + aseg * 8) * 2;
        asm volatile("st.shared.v4.b32 [%0], {%1,%2,%3,%4};" :: "r"(dst),
                     "r"(*(uint32_t*)&h0), "r"(*(uint32_t*)&h1),
                     "r"(*(uint32_t*)&h2), "r"(*(uint32_t*)&h3) : "memory");
        const __half* src = Bw + (size_t)(s * 32 + brow) * H_ + bseg;
        uint32_t d = bsu + s * BSTG + (brow * 264 + bseg) * 2;
#pragma unroll
        for (int u = 0; u < 4; u++) cp16(d + u * 16, src + u * 8);
    }
    cp_commit();
    cp_wait0();
    __syncthreads();
#pragma unroll
    for (int s = 0; s < 2; s++) {
        const uint32_t asb = asu + s * ASTG;
        const uint32_t bsb = bsu + s * BSTG;
        MMA_COMPUTE(asb, bsb)
    }
    HGEMM_EPILOGUE()
}

// ===================== layer-2 h-GEMM (fp16 A, KDIM=256, 4-stage) ===============
__global__ void __launch_bounds__(256, 2) hgemm_l2(
    const __half* __restrict__ A, const __half* __restrict__ Bw,
    const float* __restrict__ a1v, const float* __restrict__ a2v,
    __half* __restrict__ out16, float* __restrict__ s1o, float* __restrict__ s2o)
{
    extern __shared__ char dsm[];
    __shared__ float vb1[H_], vb2[H_], bb[H_];
    __shared__ float s1b[64], s2b[64];

    const int tid = threadIdx.x, wid = tid >> 5, lane = tid & 31;
    const int wm = wid >> 2, wn = wid & 3;
    const int row0 = blockIdx.x * 64;

    vb1[tid] = a1v[tid];
    vb2[tid] = a2v[tid];
    bb[tid]  = 0.f;
    if (tid < 64) { s1b[tid] = 0.f; s2b[tid] = 0.f; }
    __syncthreads();

    const uint32_t asu = smem_u32(dsm);
    const uint32_t bsu = asu + 4 * ASTG;

    float acc[2][8][4];
#pragma unroll
    for (int i = 0; i < 2; i++)
#pragma unroll
        for (int j = 0; j < 8; j++)
#pragma unroll
            for (int t = 0; t < 4; t++) acc[i][j][t] = 0.f;

    const int arow = tid >> 2, aseg = tid & 3;
    const int brow = tid >> 3, bseg = (tid & 7) * 32;
    const __half* Arow = A + (size_t)(row0 + arow) * H_ + aseg * 8;
    const uint32_t adst = asu + (arow * 40 + aseg * 8) * 2;
    const uint32_t bdst = bsu + (brow * 264 + bseg) * 2;

    auto cpTiles = [&](int s, int st) {
        cp16(adst + st * ASTG, Arow + s * 32);
        const __half* src = Bw + (size_t)(s * 32 + brow) * H_ + bseg;
        uint32_t d = bdst + st * BSTG;
#pragma unroll
        for (int u = 0; u < 4; u++) cp16(d + u * 16, src + u * 8);
        cp_commit();
    };

    constexpr int NK = H_ / 32;   // 8
    cpTiles(0, 0); cpTiles(1, 1); cpTiles(2, 2);
#pragma unroll
    for (int s = 0; s < NK; s++) {
        cp_wait2();
        __syncthreads();
        if (s + 3 < NK) cpTiles(s + 3, (s + 3) & 3);
        else            cp_commit();              // empty group: keeps retire cadence exact
        const uint32_t asb = asu + (s & 3) * ASTG;
        const uint32_t bsb = bsu + (s & 3) * BSTG;
        MMA_COMPUTE(asb, bsb)
    }
    HGEMM_EPILOGUE()
}

// ===================== stat: streaming, lane-owned mask, no warp exchange =======
// m_i = leaky(s1_i + max_{j in mask} s2_j) == exact masked row max (leaky monotone)
// E[i][j] = mask ? exp(leaky(s1_i+s2_j) - m_i) : 0; degenerate row -> E=1, l=1024
template <bool FIRST>
__global__ void __launch_bounds__(256) stat_kernel(
    const float* __restrict__ adj, const float* __restrict__ s1,
    const float* __restrict__ s2, float* __restrict__ grl, __half* __restrict__ E)
{
    __shared__ float s2s[N_];
    const int b = blockIdx.y, tid = threadIdx.x;
    const int wid = tid >> 5, lane = tid & 31;
    ((float4*)s2s)[tid] = ((const float4*)(s2 + b * N_))[tid];
    __syncthreads();

    const int row = b * N_ + blockIdx.x * 8 + wid;
    const float s1i = s1[row];

    uint32_t mymask = 0;     // bit g*4+t <-> col g*128 + lane*4 + t
    float mloc = -1e30f;

    if (FIRST) {
        const float4* ar = (const float4*)(adj + (size_t)row * N_) + lane;
#pragma unroll
        for (int g = 0; g < 8; g++) {
            float4 a = ar[g * 32];
            float4 sv = *(const float4*)&s2s[g * 128 + lane * 4];
            if (a.x > 0.f) { mymask |= 1u << (g * 4 + 0); mloc = fmaxf(mloc, sv.x); }
            if (a.y > 0.f) { mymask |= 1u << (g * 4 + 1); mloc = fmaxf(mloc, sv.y); }
            if (a.z > 0.f) { mymask |= 1u << (g * 4 + 2); mloc = fmaxf(mloc, sv.z); }
            if (a.w > 0.f) { mymask |= 1u << (g * 4 + 3); mloc = fmaxf(mloc, sv.w); }
        }
        g_mask[(size_t)row * 32 + lane] = mymask;
    } else {
        mymask = g_mask[(size_t)row * 32 + lane];
#pragma unroll
        for (int g = 0; g < 8; g++) {
            float4 sv = *(const float4*)&s2s[g * 128 + lane * 4];
            if ((mymask >> (g * 4 + 0)) & 1u) mloc = fmaxf(mloc, sv.x);
            if ((mymask >> (g * 4 + 1)) & 1u) mloc = fmaxf(mloc, sv.y);
            if ((mymask >> (g * 4 + 2)) & 1u) mloc = fmaxf(mloc, sv.z);
            if ((mymask >> (g * 4 + 3)) & 1u) mloc = fmaxf(mloc, sv.w);
        }
    }
#pragma unroll
    for (int o = 16; o > 0; o >>= 1)
        mloc = fmaxf(mloc, __shfl_xor_sync(0xffffffffu, mloc, o));

    const bool deg = (mloc < -1e29f);
    const float xm = s1i + mloc;
    const float mhat = fmaxf(xm, 0.2f * xm);

    float l = 0.f;
    __half* Erow = E + (size_t)row * N_;
#pragma unroll
    for (int g = 0; g < 8; g++) {
        float4 sv = *(const float4*)&s2s[g * 128 + lane * 4];
        float x0 = s1i + sv.x, x1 = s1i + sv.y, x2 = s1i + sv.z, x3 = s1i + sv.w;
        float e0 = ((mymask >> (g * 4 + 0)) & 1u) ? __expf(fmaxf(x0, 0.2f * x0) - mhat) : 0.f;
        float e1 = ((mymask >> (g * 4 + 1)) & 1u) ? __expf(fmaxf(x1, 0.2f * x1) - mhat) : 0.f;
        float e2 = ((mymask >> (g * 4 + 2)) & 1u) ? __expf(fmaxf(x2, 0.2f * x2) - mhat) : 0.f;
        float e3 = ((mymask >> (g * 4 + 3)) & 1u) ? __expf(fmaxf(x3, 0.2f * x3) - mhat) : 0.f;
        if (deg) { e0 = 1.f; e1 = 1.f; e2 = 1.f; e3 = 1.f; }
        __half2 h0 = __floats2half2_rn(e0, e1);
        __half2 h1 = __floats2half2_rn(e2, e3);
        uint2 w2 = { *(uint32_t*)&h0, *(uint32_t*)&h1 };
        *(uint2*)(Erow + g * 128 + lane * 4) = w2;
        l += (e0 + e1) + (e2 + e3);
    }
#pragma unroll
    for (int o = 16; o > 0; o >>= 1)
        l += __shfl_xor_sync(0xffffffffu, l, o);
    if (lane == 0) grl[row] = 1.f / l;
}

// ===================== attention: pure GEMM out = E @ h (4-stage) ===============
__global__ void __launch_bounds__(256, 2) att_mma(
    const __half* __restrict__ E, const __half* __restrict__ h16,
    const float* __restrict__ rl,
    __half* __restrict__ out16, float* __restrict__ outf)
{
    extern __shared__ char dsm[];
    const int tid = threadIdx.x, wid = tid >> 5, lane = tid & 31;
    const int wm = wid >> 2, wn = wid & 3;
    const int b = blockIdx.y, i0 = blockIdx.x * 64;

    const uint32_t asu = smem_u32(dsm);
    const uint32_t bsu = asu + 4 * ASTG;

    float acc[2][8][4];
#pragma unroll
    for (int i = 0; i < 2; i++)
#pragma unroll
        for (int j = 0; j < 8; j++)
#pragma unroll
            for (int t = 0; t < 4; t++) acc[i][j][t] = 0.f;

    const int arow = tid >> 2, aseg = tid & 3;
    const int brow = tid >> 3, bseg = (tid & 7) * 32;

    const __half* Erow = E + (size_t)(b * N_ + i0 + arow) * N_ + aseg * 8;
    const uint32_t adst = asu + (arow * 40 + aseg * 8) * 2;
    const uint32_t bdst = bsu + (brow * 264 + bseg) * 2;

    auto cpTiles = [&](int s, int st) {
        cp16(adst + st * ASTG, Erow + s * 32);
        const __half* src = h16 + (size_t)(b * N_ + s * 32 + brow) * H_ + bseg;
        uint32_t d = bdst + st * BSTG;
#pragma unroll
        for (int u = 0; u < 4; u++) cp16(d + u * 16, src + u * 8);
        cp_commit();
    };

    constexpr int NK = N_ / 32;   // 32
    cpTiles(0, 0); cpTiles(1, 1); cpTiles(2, 2);
    for (int s = 0; s < NK; s++) {
        cp_wait2();
        __syncthreads();
        if (s + 3 < NK) cpTiles(s + 3, (s + 3) & 3);
        else            cp_commit();              // empty group: keeps retire cadence exact
        const uint32_t asb = asu + (s & 3) * ASTG;
        const uint32_t bsb = bsu + (s & 3) * BSTG;
        MMA_COMPUTE(asb, bsb)
    }

    // ---------------- epilogue: scale by rl_i, relu, write ----------------
    const int r1 = lane >> 2, cq = (lane & 3) * 2;
#pragma unroll
    for (int mf = 0; mf < 2; mf++) {
#pragma unroll
        for (int rr = 0; rr < 2; rr++) {
            const int rloc = wm * 32 + mf * 16 + r1 + rr * 8;
            const int grow = b * N_ + i0 + rloc;
            const float scale = rl[grow];
#pragma unroll
            for (int nf = 0; nf < 8; nf++) {
                const int col = wn * 64 + nf * 8 + cq;
                float e0 = fmaxf(acc[mf][nf][rr * 2]     * scale, 0.f);
                float e1 = fmaxf(acc[mf][nf][rr * 2 + 1] * scale, 0.f);
                if (outf) {
                    float2 v = { e0, e1 };
                    *(float2*)(outf + (size_t)grow * H_ + col) = v;
                } else {
                    ((__half2*)out16)[((size_t)grow * H_ + col) >> 1] = __floats2half2_rn(e0, e1);
                }
            }
        }
    }
}

// ===================== pooling + MLP head =====================
__global__ void pool_partial(const float* __restrict__ x)
{
    const int b = blockIdx.y, ch = blockIdx.x, c = threadIdx.x;
    const float* p = x + (size_t)(b * N_ + ch * 128) * H_ + c;
    float s = 0.f, mx = -1e30f;
#pragma unroll 4
    for (int n = 0; n < 128; n++) {
        float v = p[(size_t)n * H_];
        s += v; mx = fmaxf(mx, v);
    }
    g_psum[(b * 8 + ch) * H_ + c] = s;
    g_pmax[(b * 8 + ch) * H_ + c] = mx;
}

__global__ void final_kernel(const float* __restrict__ W1, const float* __restrict__ b1,
                             const float* __restrict__ W2, const float* __restrict__ b2,
                             float* __restrict__ gout)
{
    __shared__ float gv[H_], g1[H_];
    const int b = blockIdx.x, c = threadIdx.x;
    float s = 0.f, mx = -1e30f;
#pragma unroll
    for (int ch = 0; ch < 8; ch++) {
        s += g_psum[(b * 8 + ch) * H_ + c];
        mx = fmaxf(mx, g_pmax[(b * 8 + ch) * H_ + c]);
    }
    gv[c] = s * (1.0f / N_) + mx;
    __syncthreads();
    float a = b1[c];
    for (int k = 0; k < H_; k++) a = fmaf(gv[k], W1[k * H_ + c], a);
    g1[c] = fmaxf(a, 0.f);
    __syncthreads();
    float a2 = b2[c];
    for (int k = 0; k < H_; k++) a2 = fmaf(g1[k], W2[k * H_ + c], a2);
    gout[b * H_ + c] = a2;
}

// ===================== launch =====================
extern "C" void kernel_launch(void* const* d_in, const int* in_sizes, int n_in,
                              void* d_out, int out_size)
{
    const float* nf   = (const float*)d_in[0];
    const float* adj  = (const float*)d_in[1];
    const float* embW = (const float*)d_in[2];
    const float* embb = (const float*)d_in[3];
    const float* W0   = (const float*)d_in[4];
    const float* a1_0 = (const float*)d_in[5];
    const float* a2_0 = (const float*)d_in[6];
    const float* W1   = (const float*)d_in[7];
    const float* a1_1 = (const float*)d_in[8];
    const float* a2_1 = (const float*)d_in[9];
    const float* gpW1 = (const float*)d_in[10];
    const float* gpb1 = (const float*)d_in[11];
    const float* gpW2 = (const float*)d_in[12];
    const float* gpb2 = (const float*)d_in[13];

    float* out  = (float*)d_out;
    float* outg = out + (size_t)B_ * N_ * H_;

    __half *pE, *px16b, *ph16, *pwf, *pw1;
    float *ps1, *ps2, *prl, *pbf;
    cudaGetSymbolAddress((void**)&pE,    g_E);
    cudaGetSymbolAddress((void**)&px16b, g_x16b);
    cudaGetSymbolAddress((void**)&ph16,  g_h16);
    cudaGetSymbolAddress((void**)&pwf,   g_wf16);
    cudaGetSymbolAddress((void**)&pw1,   g_w116);
    cudaGetSymbolAddress((void**)&pbf,   g_bf);
    cudaGetSymbolAddress((void**)&ps1,   g_s1);
    cudaGetSymbolAddress((void**)&ps2,   g_s2);
    cudaGetSymbolAddress((void**)&prl,   g_rl);

    static bool attr_done = false;
    if (!attr_done) {
        cudaFuncSetAttribute(hgemm_l2, cudaFuncAttributeMaxDynamicSharedMemorySize, STG4_BYTES);
        cudaFuncSetAttribute(att_mma,  cudaFuncAttributeMaxDynamicSharedMemorySize, STG4_BYTES);
        attr_done = true;
    }

    const int M = B_ * N_;

    prep_kernel<<<FIN_ + 1 + H_ * H_ / 256, 256>>>(embW, embb, W0, W1);

    // ---- layer 1 (embed folded into Wf; mask built inside stat) ----
    hgemm_l1<<<M / 64, 256>>>(nf, pwf, pbf, a1_0, a2_0, ph16, ps1, ps2);
    stat_kernel<true><<<dim3(N_ / 8, B_), 256>>>(adj, ps1, ps2, prl, pE);
    att_mma<<<dim3(N_ / 64, B_), 256, STG4_BYTES>>>(pE, ph16, prl, px16b, nullptr);

    // ---- layer 2 ----
    hgemm_l2<<<M / 64, 256, STG4_BYTES>>>(px16b, pw1, a1_1, a2_1, ph16, ps1, ps2);
    stat_kernel<false><<<dim3(N_ / 8, B_), 256>>>(nullptr, ps1, ps2, prl, pE);
    att_mma<<<dim3(N_ / 64, B_), 256, STG4_BYTES>>>(pE, ph16, prl, nullptr, out);

    // ---- pooling + MLP head ----
    pool_partial<<<dim3(8, B_), 256>>>(out);
    final_kernel<<<B_, 256>>>(gpW1, gpb1, gpW2, gpb2, outg);
}

// round 16
// speedup vs baseline: 1.2008x; 1.1134x over previous
#include <cuda_runtime.h>
#include <cuda_fp16.h>
#include <cstdint>

#define B_ 16
#define N_ 1024
#define FIN_ 64
#define H_ 256

// ===================== scratch (static device globals) =====================
__device__ __half    g_E    [B_ * N_ * N_];   // unnormalized masked exp (fp16), 32MB
__device__ __half    g_x16b [B_ * N_ * H_];   // layer1 output (fp16)
__device__ __half    g_h16  [B_ * N_ * H_];   // h natural layout [b][j][c]
__device__ __half    g_wf16 [FIN_ * H_];      // fused emb@W0 (fp16)
__device__ float     g_bf   [H_];             // fused bias emb_b@W0
__device__ __half    g_w116 [H_ * H_];
__device__ uint32_t  g_mask [B_ * N_ * 32];   // lane-owned: word lane, bit g*4+t <-> col g*128+lane*4+t
__device__ float     g_s1[B_ * N_], g_s2[B_ * N_], g_rl[B_ * N_];
__device__ float     g_psum[B_ * H_], g_pmax[B_ * H_];

// ===================== mma/ldmatrix/cp.async helpers (baseline PTX) ============
__device__ __forceinline__ uint32_t smem_u32(const void* p) {
    uint32_t a;
    asm("{ .reg .u64 t; cvta.to.shared.u64 t, %1; cvt.u32.u64 %0, t; }" : "=r"(a) : "l"(p));
    return a;
}
__device__ __forceinline__ void ldsm_x4(uint32_t& r0, uint32_t& r1, uint32_t& r2,
                                        uint32_t& r3, uint32_t addr) {
    asm volatile("ldmatrix.sync.aligned.m8n8.x4.shared.b16 {%0,%1,%2,%3}, [%4];"
                 : "=r"(r0), "=r"(r1), "=r"(r2), "=r"(r3) : "r"(addr));
}
__device__ __forceinline__ void ldsm_x4_t(uint32_t& r0, uint32_t& r1, uint32_t& r2,
                                          uint32_t& r3, uint32_t addr) {
    asm volatile("ldmatrix.sync.aligned.m8n8.x4.trans.shared.b16 {%0,%1,%2,%3}, [%4];"
                 : "=r"(r0), "=r"(r1), "=r"(r2), "=r"(r3) : "r"(addr));
}
__device__ __forceinline__ void mma16816(float* d, const uint32_t* a, const uint32_t* b) {
    asm volatile("mma.sync.aligned.m16n8k16.row.col.f32.f16.f16.f32 "
                 "{%0,%1,%2,%3}, {%4,%5,%6,%7}, {%8,%9}, {%0,%1,%2,%3};"
                 : "+f"(d[0]), "+f"(d[1]), "+f"(d[2]), "+f"(d[3])
                 : "r"(a[0]), "r"(a[1]), "r"(a[2]), "r"(a[3]), "r"(b[0]), "r"(b[1]));
}
__device__ __forceinline__ void cp16(uint32_t saddr, const void* gaddr) {
    asm volatile("cp.async.cg.shared.global [%0], [%1], 16;" :: "r"(saddr), "l"(gaddr));
}
__device__ __forceinline__ void cp_commit() {
    asm volatile("cp.async.commit_group;" ::: "memory");
}
__device__ __forceinline__ void cp_wait0() {
    asm volatile("cp.async.wait_group 0;" ::: "memory");
}
__device__ __forceinline__ void cp_wait2() {
    asm volatile("cp.async.wait_group 2;" ::: "memory");
}

// tile geometry
static constexpr uint32_t ASTG = 64 * 40 * 2;     // 5120 B per A stage
static constexpr uint32_t BSTG = 32 * 264 * 2;    // 16896 B per B stage (BN=256)
static constexpr uint32_t STG4_BYTES = 4 * (ASTG + BSTG);     // 88064 (hgemm_l2)
static constexpr uint32_t BSTG_ATT = 32 * 136 * 2;            // 8704 (BN=128)
static constexpr uint32_t ATT_STG4_BYTES = 4 * (ASTG + BSTG_ATT);  // 55296

// ===================== prep: Wf = emb@W0, bf = emb_b@W0, W1 fp16 ==============
__global__ void prep_kernel(const float* __restrict__ embW, const float* __restrict__ embb,
                            const float* __restrict__ W0, const float* __restrict__ W1)
{
    if (blockIdx.x < FIN_ + 1) {
        __shared__ float row[H_];
        const int f = blockIdx.x, o = threadIdx.x;
        row[o] = (f < FIN_) ? embW[f * H_ + o] : embb[o];
        __syncthreads();
        float acc = 0.f;
#pragma unroll 8
        for (int h = 0; h < H_; h++) acc = fmaf(row[h], W0[h * H_ + o], acc);
        if (f < FIN_) g_wf16[f * H_ + o] = __float2half(acc);
        else          g_bf[o] = acc;
    } else {
        int i = (blockIdx.x - (FIN_ + 1)) * 256 + threadIdx.x;
        g_w116[i] = __float2half(W1[i]);
    }
}

// ===================== shared epilogue for h-GEMMs =====================
#define HGEMM_EPILOGUE()                                                          \
    const int r1 = lane >> 2, cq = (lane & 3) * 2;                                \
    _Pragma("unroll")                                                             \
    for (int mf = 0; mf < 2; mf++) {                                              \
        _Pragma("unroll")                                                         \
        for (int rr = 0; rr < 2; rr++) {                                          \
            const int rloc = wm * 32 + mf * 16 + r1 + rr * 8;                     \
            const int grow = row0 + rloc;                                         \
            float p1 = 0.f, p2 = 0.f;                                             \
            _Pragma("unroll")                                                     \
            for (int nf = 0; nf < 8; nf++) {                                      \
                const int col = wn * 64 + nf * 8 + cq;                            \
                float e0 = acc[mf][nf][rr * 2]     + bb[col];                     \
                float e1 = acc[mf][nf][rr * 2 + 1] + bb[col + 1];                 \
                p1 = fmaf(e0, vb1[col], fmaf(e1, vb1[col + 1], p1));              \
                p2 = fmaf(e0, vb2[col], fmaf(e1, vb2[col + 1], p2));              \
                ((__half2*)out16)[((size_t)grow * H_ + col) >> 1] =               \
                    __floats2half2_rn(e0, e1);                                    \
            }                                                                     \
            p1 += __shfl_xor_sync(0xffffffffu, p1, 1);                            \
            p1 += __shfl_xor_sync(0xffffffffu, p1, 2);                            \
            p2 += __shfl_xor_sync(0xffffffffu, p2, 1);                            \
            p2 += __shfl_xor_sync(0xffffffffu, p2, 2);                            \
            if ((lane & 3) == 0) {                                                \
                atomicAdd(&s1b[rloc], p1);                                        \
                atomicAdd(&s2b[rloc], p2);                                        \
            }                                                                     \
        }                                                                         \
    }                                                                             \
    __syncthreads();                                                              \
    if (tid < 64) { s1o[row0 + tid] = s1b[tid]; s2o[row0 + tid] = s2b[tid]; }

#define MMA_COMPUTE(asb, bsb)                                                     \
    _Pragma("unroll")                                                             \
    for (int ksi = 0; ksi < 2; ksi++) {                                           \
        const int ksl = ksi * 16;                                                 \
        uint32_t af[2][4];                                                        \
        _Pragma("unroll")                                                         \
        for (int mf = 0; mf < 2; mf++) {                                          \
            int r = wm * 32 + mf * 16 + (lane & 15);                              \
            int c = ksl + (lane >> 4) * 8;                                        \
            ldsm_x4(af[mf][0], af[mf][1], af[mf][2], af[mf][3],                   \
                    (asb) + (r * 40 + c) * 2);                                    \
        }                                                                         \
        uint32_t bf[8][2];                                                        \
        _Pragma("unroll")                                                         \
        for (int ng = 0; ng < 4; ng++) {                                          \
            int r = ksl + (lane & 15);                                            \
            int c = wn * 64 + ng * 16 + (lane >> 4) * 8;                          \
            ldsm_x4_t(bf[ng * 2][0], bf[ng * 2][1],                               \
                      bf[ng * 2 + 1][0], bf[ng * 2 + 1][1],                       \
                      (bsb) + (r * 264 + c) * 2);                                 \
        }                                                                         \
        _Pragma("unroll")                                                         \
        for (int mf = 0; mf < 2; mf++)                                            \
            _Pragma("unroll")                                                     \
            for (int nf = 0; nf < 8; nf++)                                        \
                mma16816(acc[mf][nf], af[mf], bf[nf]);                            \
    }

// ===================== layer-1 h-GEMM (fp32 A, KDIM=64, 2-stage) ================
__global__ void __launch_bounds__(256, 2) hgemm_l1(
    const float* __restrict__ A, const __half* __restrict__ Bw,
    const float* __restrict__ bias, const float* __restrict__ a1v,
    const float* __restrict__ a2v,
    __half* __restrict__ out16, float* __restrict__ s1o, float* __restrict__ s2o)
{
    __shared__ __half As[2][64][40];
    __shared__ __half Bs[2][32][264];
    __shared__ float vb1[H_], vb2[H_], bb[H_];
    __shared__ float s1b[64], s2b[64];

    const int tid = threadIdx.x, wid = tid >> 5, lane = tid & 31;
    const int wm = wid >> 2, wn = wid & 3;
    const int row0 = blockIdx.x * 64;

    vb1[tid] = a1v[tid];
    vb2[tid] = a2v[tid];
    bb[tid]  = bias[tid];
    if (tid < 64) { s1b[tid] = 0.f; s2b[tid] = 0.f; }

    const uint32_t asu = smem_u32(&As[0][0][0]);
    const uint32_t bsu = smem_u32(&Bs[0][0][0]);

    float acc[2][8][4];
#pragma unroll
    for (int i = 0; i < 2; i++)
#pragma unroll
        for (int j = 0; j < 8; j++)
#pragma unroll
            for (int t = 0; t < 4; t++) acc[i][j][t] = 0.f;

    const int arow = tid >> 2, aseg = tid & 3;
    const int brow = tid >> 3, bseg = (tid & 7) * 32;

#pragma unroll
    for (int s = 0; s < 2; s++) {
        const float* p = A + (size_t)(row0 + arow) * FIN_ + s * 32 + aseg * 8;
        float4 aF0 = *(const float4*)p;
        float4 aF1 = *(const float4*)(p + 4);
        __half2 h0 = __floats2half2_rn(aF0.x, aF0.y);
        __half2 h1 = __floats2half2_rn(aF0.z, aF0.w);
        __half2 h2 = __floats2half2_rn(aF1.x, aF1.y);
        __half2 h3 = __floats2half2_rn(aF1.z, aF1.w);
        uint32_t dst = asu + s * ASTG + (arow * 40 + aseg * 8) * 2;
        asm volatile("st.shared.v4.b32 [%0], {%1,%2,%3,%4};" :: "r"(dst),
                     "r"(*(uint32_t*)&h0), "r"(*(uint32_t*)&h1),
                     "r"(*(uint32_t*)&h2), "r"(*(uint32_t*)&h3) : "memory");
        const __half* src = Bw + (size_t)(s * 32 + brow) * H_ + bseg;
        uint32_t d = bsu + s * BSTG + (brow * 264 + bseg) * 2;
#pragma unroll
        for (int u = 0; u < 4; u++) cp16(d + u * 16, src + u * 8);
    }
    cp_commit();
    cp_wait0();
    __syncthreads();
#pragma unroll
    for (int s = 0; s < 2; s++) {
        const uint32_t asb = asu + s * ASTG;
        const uint32_t bsb = bsu + s * BSTG;
        MMA_COMPUTE(asb, bsb)
    }
    HGEMM_EPILOGUE()
}

// ===================== layer-2 h-GEMM (fp16 A, KDIM=256, 4-stage) ===============
__global__ void __launch_bounds__(256, 2) hgemm_l2(
    const __half* __restrict__ A, const __half* __restrict__ Bw,
    const float* __restrict__ a1v, const float* __restrict__ a2v,
    __half* __restrict__ out16, float* __restrict__ s1o, float* __restrict__ s2o)
{
    extern __shared__ char dsm[];
    __shared__ float vb1[H_], vb2[H_], bb[H_];
    __shared__ float s1b[64], s2b[64];

    const int tid = threadIdx.x, wid = tid >> 5, lane = tid & 31;
    const int wm = wid >> 2, wn = wid & 3;
    const int row0 = blockIdx.x * 64;

    vb1[tid] = a1v[tid];
    vb2[tid] = a2v[tid];
    bb[tid]  = 0.f;
    if (tid < 64) { s1b[tid] = 0.f; s2b[tid] = 0.f; }
    __syncthreads();

    const uint32_t asu = smem_u32(dsm);
    const uint32_t bsu = asu + 4 * ASTG;

    float acc[2][8][4];
#pragma unroll
    for (int i = 0; i < 2; i++)
#pragma unroll
        for (int j = 0; j < 8; j++)
#pragma unroll
            for (int t = 0; t < 4; t++) acc[i][j][t] = 0.f;

    const int arow = tid >> 2, aseg = tid & 3;
    const int brow = tid >> 3, bseg = (tid & 7) * 32;
    const __half* Arow = A + (size_t)(row0 + arow) * H_ + aseg * 8;
    const uint32_t adst = asu + (arow * 40 + aseg * 8) * 2;
    const uint32_t bdst = bsu + (brow * 264 + bseg) * 2;

    auto cpTiles = [&](int s, int st) {
        cp16(adst + st * ASTG, Arow + s * 32);
        const __half* src = Bw + (size_t)(s * 32 + brow) * H_ + bseg;
        uint32_t d = bdst + st * BSTG;
#pragma unroll
        for (int u = 0; u < 4; u++) cp16(d + u * 16, src + u * 8);
        cp_commit();
    };

    constexpr int NK = H_ / 32;   // 8
    cpTiles(0, 0); cpTiles(1, 1); cpTiles(2, 2);
#pragma unroll
    for (int s = 0; s < NK; s++) {
        cp_wait2();
        __syncthreads();
        if (s + 3 < NK) cpTiles(s + 3, (s + 3) & 3);
        else            cp_commit();              // empty group: keeps retire cadence exact
        const uint32_t asb = asu + (s & 3) * ASTG;
        const uint32_t bsb = bsu + (s & 3) * BSTG;
        MMA_COMPUTE(asb, bsb)
    }
    HGEMM_EPILOGUE()
}

// ===================== stat: streaming, lane-owned mask, no warp exchange =======
// m_i = leaky(s1_i + max_{j in mask} s2_j) == exact masked row max (leaky monotone)
// E[i][j] = mask ? exp(leaky(s1_i+s2_j) - m_i) : 0; degenerate row -> E=1, l=1024
template <bool FIRST>
__global__ void __launch_bounds__(256) stat_kernel(
    const float* __restrict__ adj, const float* __restrict__ s1,
    const float* __restrict__ s2, float* __restrict__ grl, __half* __restrict__ E)
{
    __shared__ float s2s[N_];
    const int b = blockIdx.y, tid = threadIdx.x;
    const int wid = tid >> 5, lane = tid & 31;
    ((float4*)s2s)[tid] = ((const float4*)(s2 + b * N_))[tid];
    if (!FIRST && blockIdx.x == 0) {        // init fused-pool accumulators
        g_psum[b * H_ + tid] = 0.f;
        g_pmax[b * H_ + tid] = 0.f;
    }
    __syncthreads();

    const int row = b * N_ + blockIdx.x * 8 + wid;
    const float s1i = s1[row];

    uint32_t mymask = 0;     // bit g*4+t <-> col g*128 + lane*4 + t
    float mloc = -1e30f;

    if (FIRST) {
        const float4* ar = (const float4*)(adj + (size_t)row * N_) + lane;
#pragma unroll
        for (int g = 0; g < 8; g++) {
            float4 a = ar[g * 32];
            float4 sv = *(const float4*)&s2s[g * 128 + lane * 4];
            if (a.x > 0.f) { mymask |= 1u << (g * 4 + 0); mloc = fmaxf(mloc, sv.x); }
            if (a.y > 0.f) { mymask |= 1u << (g * 4 + 1); mloc = fmaxf(mloc, sv.y); }
            if (a.z > 0.f) { mymask |= 1u << (g * 4 + 2); mloc = fmaxf(mloc, sv.z); }
            if (a.w > 0.f) { mymask |= 1u << (g * 4 + 3); mloc = fmaxf(mloc, sv.w); }
        }
        g_mask[(size_t)row * 32 + lane] = mymask;
    } else {
        mymask = g_mask[(size_t)row * 32 + lane];
#pragma unroll
        for (int g = 0; g < 8; g++) {
            float4 sv = *(const float4*)&s2s[g * 128 + lane * 4];
            if ((mymask >> (g * 4 + 0)) & 1u) mloc = fmaxf(mloc, sv.x);
            if ((mymask >> (g * 4 + 1)) & 1u) mloc = fmaxf(mloc, sv.y);
            if ((mymask >> (g * 4 + 2)) & 1u) mloc = fmaxf(mloc, sv.z);
            if ((mymask >> (g * 4 + 3)) & 1u) mloc = fmaxf(mloc, sv.w);
        }
    }
#pragma unroll
    for (int o = 16; o > 0; o >>= 1)
        mloc = fmaxf(mloc, __shfl_xor_sync(0xffffffffu, mloc, o));

    const bool deg = (mloc < -1e29f);
    const float xm = s1i + mloc;
    const float mhat = fmaxf(xm, 0.2f * xm);

    float l = 0.f;
    __half* Erow = E + (size_t)row * N_;
#pragma unroll
    for (int g = 0; g < 8; g++) {
        float4 sv = *(const float4*)&s2s[g * 128 + lane * 4];
        float x0 = s1i + sv.x, x1 = s1i + sv.y, x2 = s1i + sv.z, x3 = s1i + sv.w;
        float e0 = ((mymask >> (g * 4 + 0)) & 1u) ? __expf(fmaxf(x0, 0.2f * x0) - mhat) : 0.f;
        float e1 = ((mymask >> (g * 4 + 1)) & 1u) ? __expf(fmaxf(x1, 0.2f * x1) - mhat) : 0.f;
        float e2 = ((mymask >> (g * 4 + 2)) & 1u) ? __expf(fmaxf(x2, 0.2f * x2) - mhat) : 0.f;
        float e3 = ((mymask >> (g * 4 + 3)) & 1u) ? __expf(fmaxf(x3, 0.2f * x3) - mhat) : 0.f;
        if (deg) { e0 = 1.f; e1 = 1.f; e2 = 1.f; e3 = 1.f; }
        __half2 h0 = __floats2half2_rn(e0, e1);
        __half2 h1 = __floats2half2_rn(e2, e3);
        uint2 w2 = { *(uint32_t*)&h0, *(uint32_t*)&h1 };
        *(uint2*)(Erow + g * 128 + lane * 4) = w2;
        l += (e0 + e1) + (e2 + e3);
    }
#pragma unroll
    for (int o = 16; o > 0; o >>= 1)
        l += __shfl_xor_sync(0xffffffffu, l, o);
    if (lane == 0) grl[row] = 1.f / l;
}

// ===================== attention: out = E @ h, 64x128 tile, 4-stage =============
// grid (N_/64, 2, B_): blockIdx.y selects the 128-col half of H.
__global__ void __launch_bounds__(256, 3) att_mma(
    const __half* __restrict__ E, const __half* __restrict__ h16,
    const float* __restrict__ rl,
    __half* __restrict__ out16, float* __restrict__ outf)
{
    extern __shared__ char dsm[];
    const int tid = threadIdx.x, wid = tid >> 5, lane = tid & 31;
    const int wm = wid >> 2, wn = wid & 3;
    const int b = blockIdx.z, i0 = blockIdx.x * 64, n0 = blockIdx.y * 128;

    const uint32_t asu = smem_u32(dsm);
    const uint32_t bsu = asu + 4 * ASTG;

    float acc[2][4][4];
#pragma unroll
    for (int i = 0; i < 2; i++)
#pragma unroll
        for (int j = 0; j < 4; j++)
#pragma unroll
            for (int t = 0; t < 4; t++) acc[i][j][t] = 0.f;

    const int arow = tid >> 2, aseg = tid & 3;          // A: 64 rows x 32
    const int brow = tid >> 3, bseg = (tid & 7) * 16;   // B: 32 rows x 128

    const __half* Erow = E + (size_t)(b * N_ + i0 + arow) * N_ + aseg * 8;
    const uint32_t adst = asu + (arow * 40 + aseg * 8) * 2;
    const uint32_t bdst = bsu + (brow * 136 + bseg) * 2;

    auto cpTiles = [&](int s, int st) {
        cp16(adst + st * ASTG, Erow + s * 32);
        const __half* src = h16 + (size_t)(b * N_ + s * 32 + brow) * H_ + n0 + bseg;
        uint32_t d = bdst + st * BSTG_ATT;
        cp16(d,      src);
        cp16(d + 16, src + 8);
        cp_commit();
    };

    constexpr int NK = N_ / 32;   // 32
    cpTiles(0, 0); cpTiles(1, 1); cpTiles(2, 2);
    for (int s = 0; s < NK; s++) {
        cp_wait2();
        __syncthreads();
        if (s + 3 < NK) cpTiles(s + 3, (s + 3) & 3);
        else            cp_commit();              // empty group: keeps retire cadence exact
        const uint32_t asb = asu + (s & 3) * ASTG;
        const uint32_t bsb = bsu + (s & 3) * BSTG_ATT;
#pragma unroll
        for (int ksi = 0; ksi < 2; ksi++) {
            const int ksl = ksi * 16;
            uint32_t af[2][4];
#pragma unroll
            for (int mf = 0; mf < 2; mf++) {
                int r = wm * 32 + mf * 16 + (lane & 15);
                int c = ksl + (lane >> 4) * 8;
                ldsm_x4(af[mf][0], af[mf][1], af[mf][2], af[mf][3],
                        asb + (r * 40 + c) * 2);
            }
            uint32_t bf[4][2];
#pragma unroll
            for (int ng = 0; ng < 2; ng++) {
                int r = ksl + (lane & 15);
                int c = wn * 32 + ng * 16 + (lane >> 4) * 8;
                ldsm_x4_t(bf[ng * 2][0], bf[ng * 2][1], bf[ng * 2 + 1][0], bf[ng * 2 + 1][1],
                          bsb + (r * 136 + c) * 2);
            }
#pragma unroll
            for (int mf = 0; mf < 2; mf++)
#pragma unroll
                for (int nf = 0; nf < 4; nf++)
                    mma16816(acc[mf][nf], af[mf], bf[nf]);
        }
    }

    // ------- epilogue: scale by rl_i, relu, write (+fused pool on fp32 path) -----
    const int r1 = lane >> 2, cq = (lane & 3) * 2;
    float scales[4];
#pragma unroll
    for (int mf = 0; mf < 2; mf++)
#pragma unroll
        for (int rr = 0; rr < 2; rr++)
            scales[mf * 2 + rr] = rl[b * N_ + i0 + wm * 32 + mf * 16 + r1 + rr * 8];

#pragma unroll
    for (int nf = 0; nf < 4; nf++) {
        const int col = n0 + wn * 32 + nf * 8 + cq;
        float ps0 = 0.f, ps1 = 0.f, pm0 = 0.f, pm1 = 0.f;
#pragma unroll
        for (int mf = 0; mf < 2; mf++) {
#pragma unroll
            for (int rr = 0; rr < 2; rr++) {
                const int grow = b * N_ + i0 + wm * 32 + mf * 16 + r1 + rr * 8;
                const float sc = scales[mf * 2 + rr];
                float e0 = fmaxf(acc[mf][nf][rr * 2]     * sc, 0.f);
                float e1 = fmaxf(acc[mf][nf][rr * 2 + 1] * sc, 0.f);
                if (outf) {
                    float2 v = { e0, e1 };
                    *(float2*)(outf + (size_t)grow * H_ + col) = v;
                    ps0 += e0; ps1 += e1;
                    pm0 = fmaxf(pm0, e0); pm1 = fmaxf(pm1, e1);
                } else {
                    ((__half2*)out16)[((size_t)grow * H_ + col) >> 1] = __floats2half2_rn(e0, e1);
                }
            }
        }
        if (outf) {
#pragma unroll
            for (int o = 4; o <= 16; o <<= 1) {
                ps0 += __shfl_xor_sync(0xffffffffu, ps0, o);
                ps1 += __shfl_xor_sync(0xffffffffu, ps1, o);
                pm0 = fmaxf(pm0, __shfl_xor_sync(0xffffffffu, pm0, o));
                pm1 = fmaxf(pm1, __shfl_xor_sync(0xffffffffu, pm1, o));
            }
            if (r1 == 0) {
                atomicAdd(&g_psum[b * H_ + col], ps0);
                atomicAdd(&g_psum[b * H_ + col + 1], ps1);
                atomicMax((int*)&g_pmax[b * H_ + col], __float_as_int(pm0));
                atomicMax((int*)&g_pmax[b * H_ + col + 1], __float_as_int(pm1));
            }
        }
    }
}

// ===================== MLP head =====================
__global__ void final_kernel(const float* __restrict__ W1, const float* __restrict__ b1,
                             const float* __restrict__ W2, const float* __restrict__ b2,
                             float* __restrict__ gout)
{
    __shared__ float gv[H_], g1[H_];
    const int b = blockIdx.x, c = threadIdx.x;
    gv[c] = g_psum[b * H_ + c] * (1.0f / N_) + g_pmax[b * H_ + c];
    __syncthreads();
    float a = b1[c];
    for (int k = 0; k < H_; k++) a = fmaf(gv[k], W1[k * H_ + c], a);
    g1[c] = fmaxf(a, 0.f);
    __syncthreads();
    float a2 = b2[c];
    for (int k = 0; k < H_; k++) a2 = fmaf(g1[k], W2[k * H_ + c], a2);
    gout[b * H_ + c] = a2;
}

// ===================== launch =====================
extern "C" void kernel_launch(void* const* d_in, const int* in_sizes, int n_in,
                              void* d_out, int out_size)
{
    const float* nf   = (const float*)d_in[0];
    const float* adj  = (const float*)d_in[1];
    const float* embW = (const float*)d_in[2];
    const float* embb = (const float*)d_in[3];
    const float* W0   = (const float*)d_in[4];
    const float* a1_0 = (const float*)d_in[5];
    const float* a2_0 = (const float*)d_in[6];
    const float* W1   = (const float*)d_in[7];
    const float* a1_1 = (const float*)d_in[8];
    const float* a2_1 = (const float*)d_in[9];
    const float* gpW1 = (const float*)d_in[10];
    const float* gpb1 = (const float*)d_in[11];
    const float* gpW2 = (const float*)d_in[12];
    const float* gpb2 = (const float*)d_in[13];

    float* out  = (float*)d_out;
    float* outg = out + (size_t)B_ * N_ * H_;

    __half *pE, *px16b, *ph16, *pwf, *pw1;
    float *ps1, *ps2, *prl, *pbf;
    cudaGetSymbolAddress((void**)&pE,    g_E);
    cudaGetSymbolAddress((void**)&px16b, g_x16b);
    cudaGetSymbolAddress((void**)&ph16,  g_h16);
    cudaGetSymbolAddress((void**)&pwf,   g_wf16);
    cudaGetSymbolAddress((void**)&pw1,   g_w116);
    cudaGetSymbolAddress((void**)&pbf,   g_bf);
    cudaGetSymbolAddress((void**)&ps1,   g_s1);
    cudaGetSymbolAddress((void**)&ps2,   g_s2);
    cudaGetSymbolAddress((void**)&prl,   g_rl);

    cudaFuncSetAttribute(hgemm_l2, cudaFuncAttributeMaxDynamicSharedMemorySize, STG4_BYTES);
    cudaFuncSetAttribute(att_mma,  cudaFuncAttributeMaxDynamicSharedMemorySize, ATT_STG4_BYTES);

    const int M = B_ * N_;
    dim3 attGrid(N_ / 64, 2, B_);

    prep_kernel<<<FIN_ + 1 + H_ * H_ / 256, 256>>>(embW, embb, W0, W1);

    // ---- layer 1 (embed folded into Wf; mask built inside stat) ----
    hgemm_l1<<<M / 64, 256>>>(nf, pwf, pbf, a1_0, a2_0, ph16, ps1, ps2);
    stat_kernel<true><<<dim3(N_ / 8, B_), 256>>>(adj, ps1, ps2, prl, pE);
    att_mma<<<attGrid, 256, ATT_STG4_BYTES>>>(pE, ph16, prl, px16b, nullptr);

    // ---- layer 2 ----
    hgemm_l2<<<M / 64, 256, STG4_BYTES>>>(px16b, pw1, a1_1, a2_1, ph16, ps1, ps2);
    stat_kernel<false><<<dim3(N_ / 8, B_), 256>>>(nullptr, ps1, ps2, prl, pE);
    att_mma<<<attGrid, 256, ATT_STG4_BYTES>>>(pE, ph16, prl, nullptr, out);

    // ---- MLP head (pool fused into att layer-2 epilogue) ----
    final_kernel<<<B_, 256>>>(gpW1, gpb1, gpW2, gpb2, outg);
}